// round 5
// baseline (speedup 1.0000x reference)
#include <cuda_runtime.h>
#include <cuda_bf16.h>
#include <cstdint>

// ============================================================================
// multimodal_attention via mma.sync (HMMA bf16 hi/lo split) on sm_103
// out[b,q,:] = softmax_k(Q.K^T) @ V       B=32, S=2048, D=64, fp32
//
// R4: cp.async double-buffered raw fp32 staging (DMA overlaps MMA section),
//     ldmatrix x4 (half the LDSM issues), dynamic smem 128KB.
// ============================================================================

#define BATCH 32
#define SEQ   2048
#define DIM   64
#define QT    128            // q rows per CTA
#define KT    64             // keys per tile
#define NTILES (SEQ / KT)    // 32
#define NTHREADS 256

// ---- dynamic smem layout ----
// raw fp32 staging, double buffered: [buf] K 16KB + V 16KB
#define RAW_K(buf)  ((buf) * 32768)
#define RAW_V(buf)  ((buf) * 32768 + 16384)
// bf16 tiles, double buffered: [buf] KHI/KLO/VHI/VLO, 8KB each
#define BF_BASE     65536
#define BF_KHI(buf) (BF_BASE + (buf) * 32768)
#define BF_KLO(buf) (BF_BASE + (buf) * 32768 + 8192)
#define BF_VHI(buf) (BF_BASE + (buf) * 32768 + 16384)
#define BF_VLO(buf) (BF_BASE + (buf) * 32768 + 24576)
#define SMEM_TOTAL  (BF_BASE + 65536)      // 131072
// Q prologue staging (transient): Qhi at BF(0)+0 (16KB), Qlo at BF(0)+16384

__device__ __forceinline__ uint32_t smem_u32(const void* p) {
    uint32_t a;
    asm("{ .reg .u64 t; cvta.to.shared.u64 t, %1; cvt.u32.u64 %0, t; }" : "=r"(a) : "l"(p));
    return a;
}
// 128B rows; xor-swizzle 16B chunks by row&7 -> conflict-free ldmatrix
__device__ __forceinline__ uint32_t swa(int row, int col16) {
    return (uint32_t)(row * 128 + ((col16 ^ (row & 7)) << 4));
}
__device__ __forceinline__ uint32_t packhi(float a, float b) {
    __nv_bfloat162 t = __floats2bfloat162_rn(a, b);
    return *reinterpret_cast<uint32_t*>(&t);
}
__device__ __forceinline__ uint32_t packlo(float a, float b) {
    float ah = __bfloat162float(__float2bfloat16_rn(a));
    float bh = __bfloat162float(__float2bfloat16_rn(b));
    __nv_bfloat162 t = __floats2bfloat162_rn(a - ah, b - bh);
    return *reinterpret_cast<uint32_t*>(&t);
}

#define CP_ASYNC16(SM, GM) \
    asm volatile("cp.async.cg.shared.global [%0], [%1], 16;" :: "r"(SM), "l"(GM) : "memory")
#define CP_COMMIT()  asm volatile("cp.async.commit_group;" ::: "memory")
#define CP_WAIT0()   asm volatile("cp.async.wait_group 0;" ::: "memory")

#define LDSM_X4(R0,R1,R2,R3,ADDR) \
    asm volatile("ldmatrix.sync.aligned.m8n8.x4.shared.b16 {%0,%1,%2,%3}, [%4];" \
                 : "=r"(R0),"=r"(R1),"=r"(R2),"=r"(R3) : "r"(ADDR))
#define LDSM_X4T(R0,R1,R2,R3,ADDR) \
    asm volatile("ldmatrix.sync.aligned.m8n8.x4.trans.shared.b16 {%0,%1,%2,%3}, [%4];" \
                 : "=r"(R0),"=r"(R1),"=r"(R2),"=r"(R3) : "r"(ADDR))
// D += A * B   (m16n8k16, bf16 in, f32 accum)
#define MMA(D,A,B0,B1) \
    asm volatile("mma.sync.aligned.m16n8k16.row.col.f32.bf16.bf16.f32 " \
                 "{%0,%1,%2,%3},{%4,%5,%6,%7},{%8,%9},{%0,%1,%2,%3};" \
                 : "+f"((D)[0]),"+f"((D)[1]),"+f"((D)[2]),"+f"((D)[3]) \
                 : "r"((A)[0]),"r"((A)[1]),"r"((A)[2]),"r"((A)[3]),"r"(B0),"r"(B1))

__global__ __launch_bounds__(NTHREADS, 1)
void attn_mma_kernel(const float* __restrict__ q,
                     const float* __restrict__ k,
                     const float* __restrict__ v,
                     float* __restrict__ out)
{
    extern __shared__ __align__(1024) char smem[];
    const uint32_t sb = smem_u32(smem);
    const int tid  = threadIdx.x;
    const int w    = tid >> 5;
    const int lane = tid & 31;
    const int b     = blockIdx.y;
    const int qbase = blockIdx.x * QT;
    const int wr0   = w * 16;                 // this warp's q-row base in tile

    const float* kb = k + (size_t)b * SEQ * DIM;
    const float* vb = v + (size_t)b * SEQ * DIM;

    // ---- kick off DMA of tile 0 before doing anything else ----
    {
        const float* kp = kb;               // tile 0
        const float* vp = vb;
#pragma unroll
        for (int i = 0; i < 4; i++) {
            uint32_t off = (uint32_t)((i * NTHREADS + tid) * 16);
            CP_ASYNC16(sb + RAW_K(0) + off, (const char*)kp + off);
            CP_ASYNC16(sb + RAW_V(0) + off, (const char*)vp + off);
        }
        CP_COMMIT();
    }

    // ---------------- Prologue: stage Q (128x64 f32 -> bf16 hi/lo) ----------
    {
        const float* qp = q + ((size_t)b * SEQ + qbase) * DIM;
#pragma unroll
        for (int i = 0; i < (QT * DIM / 4) / NTHREADS; i++) {   // 8 iters
            int idx = i * NTHREADS + tid;
            int row = idx >> 4, f4 = idx & 15;
            float4 x = reinterpret_cast<const float4*>(qp + row * DIM)[f4];
            uint32_t off = swa(row, f4 >> 1) + (f4 & 1) * 8;
            *reinterpret_cast<uint2*>(smem + BF_KHI(0) + off) =
                make_uint2(packhi(x.x, x.y), packhi(x.z, x.w));
            *reinterpret_cast<uint2*>(smem + BF_KHI(0) + 16384 + off) =
                make_uint2(packlo(x.x, x.y), packlo(x.z, x.w));
        }
    }
    __syncthreads();

    // Q fragments (A of m16n8k16): 4 k-chunks of 16, hi and lo
    uint32_t qh[4][4], ql[4][4];
    {
        int arow = wr0 + (lane & 7) + ((lane >> 3) & 1) * 8;
#pragma unroll
        for (int kc = 0; kc < 4; kc++) {
            uint32_t off = swa(arow, kc * 2 + (lane >> 4));
            LDSM_X4(qh[kc][0], qh[kc][1], qh[kc][2], qh[kc][3], sb + BF_KHI(0) + off);
            LDSM_X4(ql[kc][0], ql[kc][1], ql[kc][2], ql[kc][3], sb + BF_KHI(0) + 16384 + off);
        }
    }

    float oacc[8][4];
#pragma unroll
    for (int nt = 0; nt < 8; nt++)
#pragma unroll
        for (int i = 0; i < 4; i++) oacc[nt][i] = 0.0f;
    float ls0 = 0.0f, ls1 = 0.0f;

    // lane mapping for x4 B-operand ldmatrix
    const int m8 = lane >> 3;     // which 8x8 matrix this lane addresses
    const int r8 = lane & 7;

    for (int t = 0; t < NTILES; t++) {
        const int buf = t & 1;

        // ---- wait for tile t's raw DMA, make visible ----
        CP_WAIT0();
        __syncthreads();

        // ---- convert raw fp32 -> bf16 hi/lo swizzled tiles ----
#pragma unroll
        for (int i = 0; i < 4; i++) {
            int e   = i * NTHREADS + tid;
            int row = e >> 4, f4 = e & 15;
            uint32_t roff = (uint32_t)e * 16;
            uint32_t off  = swa(row, f4 >> 1) + (f4 & 1) * 8;
            float4 x = *reinterpret_cast<const float4*>(smem + RAW_K(buf) + roff);
            *reinterpret_cast<uint2*>(smem + BF_KHI(buf) + off) =
                make_uint2(packhi(x.x, x.y), packhi(x.z, x.w));
            *reinterpret_cast<uint2*>(smem + BF_KLO(buf) + off) =
                make_uint2(packlo(x.x, x.y), packlo(x.z, x.w));
            float4 y = *reinterpret_cast<const float4*>(smem + RAW_V(buf) + roff);
            *reinterpret_cast<uint2*>(smem + BF_VHI(buf) + off) =
                make_uint2(packhi(y.x, y.y), packhi(y.z, y.w));
            *reinterpret_cast<uint2*>(smem + BF_VLO(buf) + off) =
                make_uint2(packlo(y.x, y.y), packlo(y.z, y.w));
        }
        __syncthreads();

        // ---- prefetch tile t+1 raw (DMA overlaps the MMA section below) ----
        if (t + 1 < NTILES) {
            const float* kp = kb + (size_t)(t + 1) * KT * DIM;
            const float* vp = vb + (size_t)(t + 1) * KT * DIM;
            const int nbuf = (t + 1) & 1;
#pragma unroll
            for (int i = 0; i < 4; i++) {
                uint32_t off = (uint32_t)((i * NTHREADS + tid) * 16);
                CP_ASYNC16(sb + RAW_K(nbuf) + off, (const char*)kp + off);
                CP_ASYNC16(sb + RAW_V(nbuf) + off, (const char*)vp + off);
            }
            CP_COMMIT();
        }

        // ---- MMA1: S[16,64] = Qhi.Khi^T + Qhi.Klo^T + Qlo.Khi^T ----
        float sacc[8][4];
#pragma unroll
        for (int nt = 0; nt < 8; nt++)
#pragma unroll
            for (int i = 0; i < 4; i++) sacc[nt][i] = 0.0f;

#pragma unroll
        for (int kc = 0; kc < 4; kc++) {
#pragma unroll
            for (int ntp = 0; ntp < 4; ntp++) {
                // x4: matrices (nt,k0-7),(nt,k8-15),(nt+1,k0-7),(nt+1,k8-15)
                int krow  = (ntp * 2 + (m8 >> 1)) * 8 + r8;
                uint32_t off = swa(krow, kc * 2 + (m8 & 1));
                uint32_t bh0, bh1, bh2, bh3, bl0, bl1, bl2, bl3;
                LDSM_X4(bh0, bh1, bh2, bh3, sb + BF_KHI(buf) + off);
                LDSM_X4(bl0, bl1, bl2, bl3, sb + BF_KLO(buf) + off);
                MMA(sacc[2*ntp],   qh[kc], bh0, bh1);
                MMA(sacc[2*ntp+1], qh[kc], bh2, bh3);
                MMA(sacc[2*ntp],   qh[kc], bl0, bl1);
                MMA(sacc[2*ntp+1], qh[kc], bl2, bl3);
                MMA(sacc[2*ntp],   ql[kc], bh0, bh1);
                MMA(sacc[2*ntp+1], ql[kc], bh2, bh3);
            }
        }

        // ---- exp(S) -> P fragments (in-register: D layout == A layout) ----
        uint32_t ph[4][4], pl[4][4];
#pragma unroll
        for (int nt = 0; nt < 8; nt++) {
            float p0 = __expf(sacc[nt][0]);
            float p1 = __expf(sacc[nt][1]);
            float p2 = __expf(sacc[nt][2]);
            float p3 = __expf(sacc[nt][3]);
            ls0 += p0 + p1;
            ls1 += p2 + p3;
            int kc2 = nt >> 1, h = (nt & 1) * 2;
            ph[kc2][h]     = packhi(p0, p1);
            ph[kc2][h + 1] = packhi(p2, p3);
            pl[kc2][h]     = packlo(p0, p1);
            pl[kc2][h + 1] = packlo(p2, p3);
        }

        // ---- MMA2: O += Phi.Vhi + Phi.Vlo + Plo.Vhi  (V via ldmatrix.trans)
#pragma unroll
        for (int kc = 0; kc < 4; kc++) {
#pragma unroll
            for (int ntp = 0; ntp < 4; ntp++) {
                // x4 trans: matrices (k lo8,nt),(k hi8,nt),(k lo8,nt+1),(k hi8,nt+1)
                int vrow = kc * 16 + (m8 & 1) * 8 + r8;
                uint32_t off = swa(vrow, ntp * 2 + (m8 >> 1));
                uint32_t bh0, bh1, bh2, bh3, bl0, bl1, bl2, bl3;
                LDSM_X4T(bh0, bh1, bh2, bh3, sb + BF_VHI(buf) + off);
                LDSM_X4T(bl0, bl1, bl2, bl3, sb + BF_VLO(buf) + off);
                MMA(oacc[2*ntp],   ph[kc], bh0, bh1);
                MMA(oacc[2*ntp+1], ph[kc], bh2, bh3);
                MMA(oacc[2*ntp],   ph[kc], bl0, bl1);
                MMA(oacc[2*ntp+1], ph[kc], bl2, bl3);
                MMA(oacc[2*ntp],   pl[kc], bh0, bh1);
                MMA(oacc[2*ntp+1], pl[kc], bh2, bh3);
            }
        }
    }

    // ---- row sums: reduce over the 4 lanes of each row group ----
    ls0 += __shfl_xor_sync(0xffffffffu, ls0, 1);
    ls0 += __shfl_xor_sync(0xffffffffu, ls0, 2);
    ls1 += __shfl_xor_sync(0xffffffffu, ls1, 1);
    ls1 += __shfl_xor_sync(0xffffffffu, ls1, 2);
    const float inv0 = 1.0f / ls0;
    const float inv1 = 1.0f / ls1;

    // ---- normalize + store ----
    {
        const int r = lane >> 2, c = lane & 3;
        float* op0 = out + ((size_t)b * SEQ + qbase + wr0 + r) * DIM;
        float* op1 = op0 + 8 * DIM;
#pragma unroll
        for (int nt = 0; nt < 8; nt++) {
            float2 t0 = make_float2(oacc[nt][0] * inv0, oacc[nt][1] * inv0);
            float2 t1 = make_float2(oacc[nt][2] * inv1, oacc[nt][3] * inv1);
            *reinterpret_cast<float2*>(op0 + nt * 8 + 2 * c) = t0;
            *reinterpret_cast<float2*>(op1 + nt * 8 + 2 * c) = t1;
        }
    }
}

extern "C" void kernel_launch(void* const* d_in, const int* in_sizes, int n_in,
                              void* d_out, int out_size)
{
    const float* q = (const float*)d_in[0];
    const float* k = (const float*)d_in[1];
    const float* v = (const float*)d_in[2];
    float* out = (float*)d_out;

    cudaFuncSetAttribute(attn_mma_kernel,
                         cudaFuncAttributeMaxDynamicSharedMemorySize, SMEM_TOTAL);
    dim3 grid(SEQ / QT, BATCH);
    attn_mma_kernel<<<grid, NTHREADS, SMEM_TOTAL>>>(q, k, v, out);
}

// round 7
// speedup vs baseline: 1.0949x; 1.0949x over previous
#include <cuda_runtime.h>
#include <cuda_bf16.h>
#include <cstdint>

// ============================================================================
// multimodal_attention via mma.sync (HMMA bf16 hi/lo split) on sm_103
// out[b,q,:] = softmax_k(Q.K^T) @ V       B=32, S=2048, D=64, fp32
//
// R6: identical to R5 (bench infra failed; retry). 128-thread CTAs (QT=64),
//     __launch_bounds__(128,3) -> 3 CTAs/SM so convert/exp/sync phases of one
//     CTA overlap MMA of the others. Direct LDG->cvt->STS staging, x4 ldmatrix.
// ============================================================================

#define BATCH 32
#define SEQ   2048
#define DIM   64
#define QT    64             // q rows per CTA
#define KT    64             // keys per tile
#define NTILES (SEQ / KT)    // 32
#define NTHREADS 128

// smem: four 64x64 bf16 tiles, 128B rows, xor-swizzled (8KB each) = 32KB
#define SM_KHI 0
#define SM_KLO 8192
#define SM_VHI 16384
#define SM_VLO 24576
// Q staging (prologue only): Qhi at 0 (8KB), Qlo at 16384 (8KB)

__device__ __forceinline__ uint32_t smem_u32(const void* p) {
    uint32_t a;
    asm("{ .reg .u64 t; cvta.to.shared.u64 t, %1; cvt.u32.u64 %0, t; }" : "=r"(a) : "l"(p));
    return a;
}
// 128B rows; xor-swizzle 16B chunks by row&7 -> conflict-free ldmatrix
__device__ __forceinline__ uint32_t swa(int row, int col16) {
    return (uint32_t)(row * 128 + ((col16 ^ (row & 7)) << 4));
}
__device__ __forceinline__ uint32_t packhi(float a, float b) {
    __nv_bfloat162 t = __floats2bfloat162_rn(a, b);
    return *reinterpret_cast<uint32_t*>(&t);
}
__device__ __forceinline__ uint32_t packlo(float a, float b) {
    float ah = __bfloat162float(__float2bfloat16_rn(a));
    float bh = __bfloat162float(__float2bfloat16_rn(b));
    __nv_bfloat162 t = __floats2bfloat162_rn(a - ah, b - bh);
    return *reinterpret_cast<uint32_t*>(&t);
}

#define LDSM_X4(R0,R1,R2,R3,ADDR) \
    asm volatile("ldmatrix.sync.aligned.m8n8.x4.shared.b16 {%0,%1,%2,%3}, [%4];" \
                 : "=r"(R0),"=r"(R1),"=r"(R2),"=r"(R3) : "r"(ADDR))
#define LDSM_X4T(R0,R1,R2,R3,ADDR) \
    asm volatile("ldmatrix.sync.aligned.m8n8.x4.trans.shared.b16 {%0,%1,%2,%3}, [%4];" \
                 : "=r"(R0),"=r"(R1),"=r"(R2),"=r"(R3) : "r"(ADDR))
// D += A * B   (m16n8k16, bf16 in, f32 accum)
#define MMA(D,A,B0,B1) \
    asm volatile("mma.sync.aligned.m16n8k16.row.col.f32.bf16.bf16.f32 " \
                 "{%0,%1,%2,%3},{%4,%5,%6,%7},{%8,%9},{%0,%1,%2,%3};" \
                 : "+f"((D)[0]),"+f"((D)[1]),"+f"((D)[2]),"+f"((D)[3]) \
                 : "r"((A)[0]),"r"((A)[1]),"r"((A)[2]),"r"((A)[3]),"r"(B0),"r"(B1))

__global__ __launch_bounds__(NTHREADS, 3)
void attn_mma_kernel(const float* __restrict__ q,
                     const float* __restrict__ k,
                     const float* __restrict__ v,
                     float* __restrict__ out)
{
    __shared__ __align__(1024) char smem[32768];
    const uint32_t sb = smem_u32(smem);
    const int tid  = threadIdx.x;
    const int w    = tid >> 5;                // warp 0..3
    const int lane = tid & 31;
    const int b     = blockIdx.y;
    const int qbase = blockIdx.x * QT;
    const int wr0   = w * 16;                 // this warp's q-row base in tile

    // ---------------- Prologue: stage Q (64x64 f32 -> bf16 hi/lo) ----------
    {
        const float* qp = q + ((size_t)b * SEQ + qbase) * DIM;
#pragma unroll
        for (int i = 0; i < (QT * DIM / 4) / NTHREADS; i++) {   // 8 iters
            int idx = i * NTHREADS + tid;
            int row = idx >> 4, f4 = idx & 15;
            float4 x = reinterpret_cast<const float4*>(qp + row * DIM)[f4];
            uint32_t off = swa(row, f4 >> 1) + (f4 & 1) * 8;
            *reinterpret_cast<uint2*>(smem + off) =
                make_uint2(packhi(x.x, x.y), packhi(x.z, x.w));
            *reinterpret_cast<uint2*>(smem + 16384 + off) =
                make_uint2(packlo(x.x, x.y), packlo(x.z, x.w));
        }
    }
    __syncthreads();

    // Q fragments (A of m16n8k16): 4 k-chunks of 16, hi and lo
    uint32_t qh[4][4], ql[4][4];
    {
        int arow = wr0 + (lane & 7) + ((lane >> 3) & 1) * 8;
#pragma unroll
        for (int kc = 0; kc < 4; kc++) {
            uint32_t off = swa(arow, kc * 2 + (lane >> 4));
            LDSM_X4(qh[kc][0], qh[kc][1], qh[kc][2], qh[kc][3], sb + off);
            LDSM_X4(ql[kc][0], ql[kc][1], ql[kc][2], ql[kc][3], sb + 16384 + off);
        }
    }

    float oacc[8][4];
#pragma unroll
    for (int nt = 0; nt < 8; nt++)
#pragma unroll
        for (int i = 0; i < 4; i++) oacc[nt][i] = 0.0f;
    float ls0 = 0.0f, ls1 = 0.0f;

    const float* kb = k + (size_t)b * SEQ * DIM;
    const float* vb = v + (size_t)b * SEQ * DIM;

    // lane mapping for x4 B-operand ldmatrix
    const int m8 = lane >> 3;     // which 8x8 matrix this lane addresses
    const int r8 = lane & 7;

    for (int t = 0; t < NTILES; t++) {
        __syncthreads();   // previous tile's smem reads complete (Q frags on t=0)

        // ---- stage K,V tile: f32 -> bf16 hi/lo, swizzled ----
        const float* kp = kb + (size_t)t * KT * DIM;
        const float* vp = vb + (size_t)t * KT * DIM;
#pragma unroll
        for (int i = 0; i < (KT * DIM / 4) / NTHREADS; i++) {   // 8 iters
            int idx = i * NTHREADS + tid;
            int row = idx >> 4, f4 = idx & 15;
            uint32_t off = swa(row, f4 >> 1) + (f4 & 1) * 8;
            float4 x = reinterpret_cast<const float4*>(kp + row * DIM)[f4];
            *reinterpret_cast<uint2*>(smem + SM_KHI + off) =
                make_uint2(packhi(x.x, x.y), packhi(x.z, x.w));
            *reinterpret_cast<uint2*>(smem + SM_KLO + off) =
                make_uint2(packlo(x.x, x.y), packlo(x.z, x.w));
            float4 y = reinterpret_cast<const float4*>(vp + row * DIM)[f4];
            *reinterpret_cast<uint2*>(smem + SM_VHI + off) =
                make_uint2(packhi(y.x, y.y), packhi(y.z, y.w));
            *reinterpret_cast<uint2*>(smem + SM_VLO + off) =
                make_uint2(packlo(y.x, y.y), packlo(y.z, y.w));
        }
        __syncthreads();

        // ---- MMA1: S[16,64] = Qhi.Khi^T + Qhi.Klo^T + Qlo.Khi^T ----
        float sacc[8][4];
#pragma unroll
        for (int nt = 0; nt < 8; nt++)
#pragma unroll
            for (int i = 0; i < 4; i++) sacc[nt][i] = 0.0f;

#pragma unroll
        for (int kc = 0; kc < 4; kc++) {
#pragma unroll
            for (int ntp = 0; ntp < 4; ntp++) {
                // x4: matrices (nt,k0-7),(nt,k8-15),(nt+1,k0-7),(nt+1,k8-15)
                int krow  = (ntp * 2 + (m8 >> 1)) * 8 + r8;
                uint32_t off = swa(krow, kc * 2 + (m8 & 1));
                uint32_t bh0, bh1, bh2, bh3, bl0, bl1, bl2, bl3;
                LDSM_X4(bh0, bh1, bh2, bh3, sb + SM_KHI + off);
                LDSM_X4(bl0, bl1, bl2, bl3, sb + SM_KLO + off);
                MMA(sacc[2*ntp],   qh[kc], bh0, bh1);
                MMA(sacc[2*ntp+1], qh[kc], bh2, bh3);
                MMA(sacc[2*ntp],   qh[kc], bl0, bl1);
                MMA(sacc[2*ntp+1], qh[kc], bl2, bl3);
                MMA(sacc[2*ntp],   ql[kc], bh0, bh1);
                MMA(sacc[2*ntp+1], ql[kc], bh2, bh3);
            }
        }

        // ---- exp(S) -> P fragments (in-register: D layout == A layout) ----
        uint32_t ph[4][4], pl[4][4];
#pragma unroll
        for (int nt = 0; nt < 8; nt++) {
            float p0 = __expf(sacc[nt][0]);
            float p1 = __expf(sacc[nt][1]);
            float p2 = __expf(sacc[nt][2]);
            float p3 = __expf(sacc[nt][3]);
            ls0 += p0 + p1;
            ls1 += p2 + p3;
            int kc2 = nt >> 1, h = (nt & 1) * 2;
            ph[kc2][h]     = packhi(p0, p1);
            ph[kc2][h + 1] = packhi(p2, p3);
            pl[kc2][h]     = packlo(p0, p1);
            pl[kc2][h + 1] = packlo(p2, p3);
        }

        // ---- MMA2: O += Phi.Vhi + Phi.Vlo + Plo.Vhi  (V via ldmatrix.trans)
#pragma unroll
        for (int kc = 0; kc < 4; kc++) {
#pragma unroll
            for (int ntp = 0; ntp < 4; ntp++) {
                int vrow = kc * 16 + (m8 & 1) * 8 + r8;
                uint32_t off = swa(vrow, ntp * 2 + (m8 >> 1));
                uint32_t bh0, bh1, bh2, bh3, bl0, bl1, bl2, bl3;
                LDSM_X4T(bh0, bh1, bh2, bh3, sb + SM_VHI + off);
                LDSM_X4T(bl0, bl1, bl2, bl3, sb + SM_VLO + off);
                MMA(oacc[2*ntp],   ph[kc], bh0, bh1);
                MMA(oacc[2*ntp+1], ph[kc], bh2, bh3);
                MMA(oacc[2*ntp],   ph[kc], bl0, bl1);
                MMA(oacc[2*ntp+1], ph[kc], bl2, bl3);
                MMA(oacc[2*ntp],   pl[kc], bh0, bh1);
                MMA(oacc[2*ntp+1], pl[kc], bh2, bh3);
            }
        }
    }

    // ---- row sums: reduce over the 4 lanes of each row group ----
    ls0 += __shfl_xor_sync(0xffffffffu, ls0, 1);
    ls0 += __shfl_xor_sync(0xffffffffu, ls0, 2);
    ls1 += __shfl_xor_sync(0xffffffffu, ls1, 1);
    ls1 += __shfl_xor_sync(0xffffffffu, ls1, 2);
    const float inv0 = 1.0f / ls0;
    const float inv1 = 1.0f / ls1;

    // ---- normalize + store ----
    {
        const int r = lane >> 2, c = lane & 3;
        float* op0 = out + ((size_t)b * SEQ + qbase + wr0 + r) * DIM;
        float* op1 = op0 + 8 * DIM;
#pragma unroll
        for (int nt = 0; nt < 8; nt++) {
            float2 t0 = make_float2(oacc[nt][0] * inv0, oacc[nt][1] * inv0);
            float2 t1 = make_float2(oacc[nt][2] * inv1, oacc[nt][3] * inv1);
            *reinterpret_cast<float2*>(op0 + nt * 8 + 2 * c) = t0;
            *reinterpret_cast<float2*>(op1 + nt * 8 + 2 * c) = t1;
        }
    }
}

extern "C" void kernel_launch(void* const* d_in, const int* in_sizes, int n_in,
                              void* d_out, int out_size)
{
    const float* q = (const float*)d_in[0];
    const float* k = (const float*)d_in[1];
    const float* v = (const float*)d_in[2];
    float* out = (float*)d_out;

    dim3 grid(SEQ / QT, BATCH);
    attn_mma_kernel<<<grid, NTHREADS>>>(q, k, v, out);
}

// round 8
// speedup vs baseline: 1.4160x; 1.2933x over previous
#include <cuda_runtime.h>
#include <cuda_bf16.h>
#include <cstdint>

// ============================================================================
// multimodal_attention via mma.sync (HMMA bf16 hi/lo split) on sm_103
// out[b,q,:] = softmax_k(Q.K^T) @ V       B=32, S=2048, D=64, fp32
//
// R7: two-kernel scheme.
//  1) prepass: K,V fp32 -> bf16 hi/lo into __device__ global scratch (once).
//  2) attention: cp.async DMA of preconverted bf16 straight into swizzled
//     smem (double buffered), zero conversion in the hot loop.
// ============================================================================

#define BATCH 32
#define SEQ   2048
#define DIM   64
#define QT    64             // q rows per CTA
#define KT    64             // keys per tile
#define NTILES (SEQ / KT)    // 32
#define NTHREADS 128

#define KV_ELEMS (BATCH * SEQ * DIM)     // 4,194,304

// preconverted K/V scratch (32 MB total)
__device__ __nv_bfloat16 g_khi[KV_ELEMS];
__device__ __nv_bfloat16 g_klo[KV_ELEMS];
__device__ __nv_bfloat16 g_vhi[KV_ELEMS];
__device__ __nv_bfloat16 g_vlo[KV_ELEMS];

// smem: double buffer, each buf = {KHI,KLO,VHI,VLO} 8KB tiles = 32KB
#define BUF_STRIDE 32768
#define T_KHI 0
#define T_KLO 8192
#define T_VHI 16384
#define T_VLO 24576
#define SMEM_BYTES (2 * BUF_STRIDE)      // 64KB static

__device__ __forceinline__ uint32_t smem_u32(const void* p) {
    uint32_t a;
    asm("{ .reg .u64 t; cvta.to.shared.u64 t, %1; cvt.u32.u64 %0, t; }" : "=r"(a) : "l"(p));
    return a;
}
// 128B rows; xor-swizzle 16B chunks by row&7 -> conflict-free ldmatrix
__device__ __forceinline__ uint32_t swa(int row, int col16) {
    return (uint32_t)(row * 128 + ((col16 ^ (row & 7)) << 4));
}
__device__ __forceinline__ uint32_t packhi(float a, float b) {
    __nv_bfloat162 t = __floats2bfloat162_rn(a, b);
    return *reinterpret_cast<uint32_t*>(&t);
}
__device__ __forceinline__ uint32_t packlo(float a, float b) {
    float ah = __bfloat162float(__float2bfloat16_rn(a));
    float bh = __bfloat162float(__float2bfloat16_rn(b));
    __nv_bfloat162 t = __floats2bfloat162_rn(a - ah, b - bh);
    return *reinterpret_cast<uint32_t*>(&t);
}

#define CP_ASYNC16(SM, GM) \
    asm volatile("cp.async.cg.shared.global [%0], [%1], 16;" :: "r"(SM), "l"(GM) : "memory")
#define CP_COMMIT()  asm volatile("cp.async.commit_group;" ::: "memory")
#define CP_WAIT0()   asm volatile("cp.async.wait_group 0;" ::: "memory")
#define CP_WAIT1()   asm volatile("cp.async.wait_group 1;" ::: "memory")

#define LDSM_X4(R0,R1,R2,R3,ADDR) \
    asm volatile("ldmatrix.sync.aligned.m8n8.x4.shared.b16 {%0,%1,%2,%3}, [%4];" \
                 : "=r"(R0),"=r"(R1),"=r"(R2),"=r"(R3) : "r"(ADDR))
#define LDSM_X4T(R0,R1,R2,R3,ADDR) \
    asm volatile("ldmatrix.sync.aligned.m8n8.x4.trans.shared.b16 {%0,%1,%2,%3}, [%4];" \
                 : "=r"(R0),"=r"(R1),"=r"(R2),"=r"(R3) : "r"(ADDR))
// D += A * B   (m16n8k16, bf16 in, f32 accum)
#define MMA(D,A,B0,B1) \
    asm volatile("mma.sync.aligned.m16n8k16.row.col.f32.bf16.bf16.f32 " \
                 "{%0,%1,%2,%3},{%4,%5,%6,%7},{%8,%9},{%0,%1,%2,%3};" \
                 : "+f"((D)[0]),"+f"((D)[1]),"+f"((D)[2]),"+f"((D)[3]) \
                 : "r"((A)[0]),"r"((A)[1]),"r"((A)[2]),"r"((A)[3]),"r"(B0),"r"(B1))

// ---------------------------------------------------------------------------
// Pre-pass: K,V fp32 -> bf16 hi/lo scratch.  4 fp32 per thread per tensor.
// ---------------------------------------------------------------------------
__global__ __launch_bounds__(256)
void kv_convert_kernel(const float* __restrict__ k, const float* __restrict__ v)
{
    int i = blockIdx.x * 256 + threadIdx.x;          // float4 index
    float4 kx = reinterpret_cast<const float4*>(k)[i];
    float4 vx = reinterpret_cast<const float4*>(v)[i];
    reinterpret_cast<uint2*>(g_khi)[i] = make_uint2(packhi(kx.x, kx.y), packhi(kx.z, kx.w));
    reinterpret_cast<uint2*>(g_klo)[i] = make_uint2(packlo(kx.x, kx.y), packlo(kx.z, kx.w));
    reinterpret_cast<uint2*>(g_vhi)[i] = make_uint2(packhi(vx.x, vx.y), packhi(vx.z, vx.w));
    reinterpret_cast<uint2*>(g_vlo)[i] = make_uint2(packlo(vx.x, vx.y), packlo(vx.z, vx.w));
}

// ---------------------------------------------------------------------------
// Attention kernel
// ---------------------------------------------------------------------------
__global__ __launch_bounds__(NTHREADS, 3)
void attn_mma_kernel(const float* __restrict__ q,
                     float* __restrict__ out)
{
    __shared__ __align__(1024) char smem[SMEM_BYTES];
    const uint32_t sb = smem_u32(smem);
    const int tid  = threadIdx.x;
    const int w    = tid >> 5;                // warp 0..3
    const int lane = tid & 31;
    const int b     = blockIdx.y;
    const int qbase = blockIdx.x * QT;
    const int wr0   = w * 16;                 // this warp's q-row base in tile

    const size_t kvbase = (size_t)b * SEQ * DIM;   // element offset of this batch

    // per-thread cp.async chunk mapping: 16 chunks of 16B per tile
    // i in 0..15; array = i>>2 (0:KHI 1:KLO 2:VHI 3:VLO); rc = (i&3)*128+tid
    // row = rc>>3 (0..63), col16 = rc&7
    const __nv_bfloat16* g_arr[4] = { g_khi, g_klo, g_vhi, g_vlo };

    // ---- kick off DMA of tile 0 into buf0 ----
    {
#pragma unroll
        for (int i = 0; i < 16; i++) {
            int arr = i >> 2, rc = (i & 3) * NTHREADS + tid;
            int row = rc >> 3, c16 = rc & 7;
            const char* src = (const char*)(g_arr[arr] + kvbase + row * DIM) + c16 * 16;
            CP_ASYNC16(sb + arr * 8192 + swa(row, c16), src);
        }
        CP_COMMIT();
    }

    // ---- Prologue: stage Q (64x64 f32 -> bf16 hi/lo) into buf1 region ----
    {
        const float* qp = q + ((size_t)b * SEQ + qbase) * DIM;
#pragma unroll
        for (int i = 0; i < (QT * DIM / 4) / NTHREADS; i++) {   // 8 iters
            int idx = i * NTHREADS + tid;
            int row = idx >> 4, f4 = idx & 15;
            float4 x = reinterpret_cast<const float4*>(qp + row * DIM)[f4];
            uint32_t off = swa(row, f4 >> 1) + (f4 & 1) * 8;
            *reinterpret_cast<uint2*>(smem + BUF_STRIDE + off) =
                make_uint2(packhi(x.x, x.y), packhi(x.z, x.w));
            *reinterpret_cast<uint2*>(smem + BUF_STRIDE + 8192 + off) =
                make_uint2(packlo(x.x, x.y), packlo(x.z, x.w));
        }
    }
    __syncthreads();

    // Q fragments (A of m16n8k16): 4 k-chunks of 16, hi and lo
    uint32_t qh[4][4], ql[4][4];
    {
        int arow = wr0 + (lane & 7) + ((lane >> 3) & 1) * 8;
#pragma unroll
        for (int kc = 0; kc < 4; kc++) {
            uint32_t off = swa(arow, kc * 2 + (lane >> 4));
            LDSM_X4(qh[kc][0], qh[kc][1], qh[kc][2], qh[kc][3], sb + BUF_STRIDE + off);
            LDSM_X4(ql[kc][0], ql[kc][1], ql[kc][2], ql[kc][3], sb + BUF_STRIDE + 8192 + off);
        }
    }
    __syncthreads();   // buf1 free for tile-1 prefetch after this

    float oacc[8][4];
#pragma unroll
    for (int nt = 0; nt < 8; nt++)
#pragma unroll
        for (int i = 0; i < 4; i++) oacc[nt][i] = 0.0f;
    float ls0 = 0.0f, ls1 = 0.0f;

    // lane mapping for x4 B-operand ldmatrix
    const int m8 = lane >> 3;     // which 8x8 matrix this lane addresses
    const int r8 = lane & 7;

    for (int t = 0; t < NTILES; t++) {
        const uint32_t bufb = sb + (uint32_t)(t & 1) * BUF_STRIDE;

        // ---- prefetch tile t+1 into the other buffer; wait for tile t ----
        if (t + 1 < NTILES) {
            const size_t toff = kvbase + (size_t)(t + 1) * KT * DIM;
            const uint32_t nb = sb + (uint32_t)((t + 1) & 1) * BUF_STRIDE;
#pragma unroll
            for (int i = 0; i < 16; i++) {
                int arr = i >> 2, rc = (i & 3) * NTHREADS + tid;
                int row = rc >> 3, c16 = rc & 7;
                const char* src = (const char*)(g_arr[arr] + toff + row * DIM) + c16 * 16;
                CP_ASYNC16(nb + arr * 8192 + swa(row, c16), src);
            }
            CP_COMMIT();
            CP_WAIT1();          // oldest group (tile t) complete
        } else {
            CP_WAIT0();
        }
        __syncthreads();

        // ---- MMA1: S[16,64] = Qhi.Khi^T + Qhi.Klo^T + Qlo.Khi^T ----
        float sacc[8][4];
#pragma unroll
        for (int nt = 0; nt < 8; nt++)
#pragma unroll
            for (int i = 0; i < 4; i++) sacc[nt][i] = 0.0f;

#pragma unroll
        for (int kc = 0; kc < 4; kc++) {
#pragma unroll
            for (int ntp = 0; ntp < 4; ntp++) {
                int krow  = (ntp * 2 + (m8 >> 1)) * 8 + r8;
                uint32_t off = swa(krow, kc * 2 + (m8 & 1));
                uint32_t bh0, bh1, bh2, bh3, bl0, bl1, bl2, bl3;
                LDSM_X4(bh0, bh1, bh2, bh3, bufb + T_KHI + off);
                LDSM_X4(bl0, bl1, bl2, bl3, bufb + T_KLO + off);
                MMA(sacc[2*ntp],   qh[kc], bh0, bh1);
                MMA(sacc[2*ntp+1], qh[kc], bh2, bh3);
                MMA(sacc[2*ntp],   qh[kc], bl0, bl1);
                MMA(sacc[2*ntp+1], qh[kc], bl2, bl3);
                MMA(sacc[2*ntp],   ql[kc], bh0, bh1);
                MMA(sacc[2*ntp+1], ql[kc], bh2, bh3);
            }
        }

        // ---- exp(S) -> P fragments (in-register: D layout == A layout) ----
        uint32_t ph[4][4], pl[4][4];
#pragma unroll
        for (int nt = 0; nt < 8; nt++) {
            float p0 = __expf(sacc[nt][0]);
            float p1 = __expf(sacc[nt][1]);
            float p2 = __expf(sacc[nt][2]);
            float p3 = __expf(sacc[nt][3]);
            ls0 += p0 + p1;
            ls1 += p2 + p3;
            int kc2 = nt >> 1, h = (nt & 1) * 2;
            ph[kc2][h]     = packhi(p0, p1);
            ph[kc2][h + 1] = packhi(p2, p3);
            pl[kc2][h]     = packlo(p0, p1);
            pl[kc2][h + 1] = packlo(p2, p3);
        }

        // ---- MMA2: O += Phi.Vhi + Phi.Vlo + Plo.Vhi  (V via ldmatrix.trans)
#pragma unroll
        for (int kc = 0; kc < 4; kc++) {
#pragma unroll
            for (int ntp = 0; ntp < 4; ntp++) {
                int vrow = kc * 16 + (m8 & 1) * 8 + r8;
                uint32_t off = swa(vrow, ntp * 2 + (m8 >> 1));
                uint32_t bh0, bh1, bh2, bh3, bl0, bl1, bl2, bl3;
                LDSM_X4T(bh0, bh1, bh2, bh3, bufb + T_VHI + off);
                LDSM_X4T(bl0, bl1, bl2, bl3, bufb + T_VLO + off);
                MMA(oacc[2*ntp],   ph[kc], bh0, bh1);
                MMA(oacc[2*ntp+1], ph[kc], bh2, bh3);
                MMA(oacc[2*ntp],   ph[kc], bl0, bl1);
                MMA(oacc[2*ntp+1], ph[kc], bl2, bl3);
                MMA(oacc[2*ntp],   pl[kc], bh0, bh1);
                MMA(oacc[2*ntp+1], pl[kc], bh2, bh3);
            }
        }
        __syncthreads();   // tile t reads done -> buffer reusable next iter
    }

    // ---- row sums: reduce over the 4 lanes of each row group ----
    ls0 += __shfl_xor_sync(0xffffffffu, ls0, 1);
    ls0 += __shfl_xor_sync(0xffffffffu, ls0, 2);
    ls1 += __shfl_xor_sync(0xffffffffu, ls1, 1);
    ls1 += __shfl_xor_sync(0xffffffffu, ls1, 2);
    const float inv0 = 1.0f / ls0;
    const float inv1 = 1.0f / ls1;

    // ---- normalize + store ----
    {
        const int r = lane >> 2, c = lane & 3;
        float* op0 = out + ((size_t)b * SEQ + qbase + wr0 + r) * DIM;
        float* op1 = op0 + 8 * DIM;
#pragma unroll
        for (int nt = 0; nt < 8; nt++) {
            float2 t0 = make_float2(oacc[nt][0] * inv0, oacc[nt][1] * inv0);
            float2 t1 = make_float2(oacc[nt][2] * inv1, oacc[nt][3] * inv1);
            *reinterpret_cast<float2*>(op0 + nt * 8 + 2 * c) = t0;
            *reinterpret_cast<float2*>(op1 + nt * 8 + 2 * c) = t1;
        }
    }
}

extern "C" void kernel_launch(void* const* d_in, const int* in_sizes, int n_in,
                              void* d_out, int out_size)
{
    const float* q = (const float*)d_in[0];
    const float* k = (const float*)d_in[1];
    const float* v = (const float*)d_in[2];
    float* out = (float*)d_out;

    kv_convert_kernel<<<KV_ELEMS / 4 / 256, 256>>>(k, v);

    dim3 grid(SEQ / QT, BATCH);
    attn_mma_kernel<<<grid, NTHREADS>>>(q, out);
}

// round 10
// speedup vs baseline: 1.4649x; 1.0345x over previous
#include <cuda_runtime.h>
#include <cuda_bf16.h>
#include <cstdint>

// ============================================================================
// multimodal_attention via mma.sync (HMMA bf16 hi/lo split) on sm_103
// out[b,q,:] = softmax_k(Q.K^T) @ V       B=32, S=2048, D=64, fp32
//
// R9: identical to R8 (bench infra failed twice; retry).
//     prepass folds log2e into K (hot loop uses raw ex2.approx);
//     truncation-based P split (PRMT/LOP/FADD, fewer instrs);
//     half-split software pipeline so exp overlaps tensor execution.
// ============================================================================

#define BATCH 32
#define SEQ   2048
#define DIM   64
#define QT    64             // q rows per CTA
#define KT    64             // keys per tile
#define NTILES (SEQ / KT)    // 32
#define NTHREADS 128

#define KV_ELEMS (BATCH * SEQ * DIM)     // 4,194,304

// preconverted K/V scratch (32 MB total); K pre-scaled by log2(e)
__device__ __nv_bfloat16 g_khi[KV_ELEMS];
__device__ __nv_bfloat16 g_klo[KV_ELEMS];
__device__ __nv_bfloat16 g_vhi[KV_ELEMS];
__device__ __nv_bfloat16 g_vlo[KV_ELEMS];

// smem: double buffer, each buf = {KHI,KLO,VHI,VLO} 8KB tiles = 32KB
#define BUF_STRIDE 32768
#define T_KHI 0
#define T_KLO 8192
#define T_VHI 16384
#define T_VLO 24576
#define SMEM_BYTES (2 * BUF_STRIDE)      // 64KB static

__device__ __forceinline__ uint32_t smem_u32(const void* p) {
    uint32_t a;
    asm("{ .reg .u64 t; cvta.to.shared.u64 t, %1; cvt.u32.u64 %0, t; }" : "=r"(a) : "l"(p));
    return a;
}
// 128B rows; xor-swizzle 16B chunks by row&7 -> conflict-free ldmatrix
__device__ __forceinline__ uint32_t swa(int row, int col16) {
    return (uint32_t)(row * 128 + ((col16 ^ (row & 7)) << 4));
}
__device__ __forceinline__ uint32_t packhi(float a, float b) {
    __nv_bfloat162 t = __floats2bfloat162_rn(a, b);
    return *reinterpret_cast<uint32_t*>(&t);
}
__device__ __forceinline__ uint32_t packlo(float a, float b) {
    float ah = __bfloat162float(__float2bfloat16_rn(a));
    float bh = __bfloat162float(__float2bfloat16_rn(b));
    __nv_bfloat162 t = __floats2bfloat162_rn(a - ah, b - bh);
    return *reinterpret_cast<uint32_t*>(&t);
}
__device__ __forceinline__ float ex2f(float x) {
    float r;
    asm("ex2.approx.ftz.f32 %0, %1;" : "=f"(r) : "f"(x));
    return r;
}

#define CP_ASYNC16(SM, GM) \
    asm volatile("cp.async.cg.shared.global [%0], [%1], 16;" :: "r"(SM), "l"(GM) : "memory")
#define CP_COMMIT()  asm volatile("cp.async.commit_group;" ::: "memory")
#define CP_WAIT0()   asm volatile("cp.async.wait_group 0;" ::: "memory")
#define CP_WAIT1()   asm volatile("cp.async.wait_group 1;" ::: "memory")

#define LDSM_X4(R0,R1,R2,R3,ADDR) \
    asm volatile("ldmatrix.sync.aligned.m8n8.x4.shared.b16 {%0,%1,%2,%3}, [%4];" \
                 : "=r"(R0),"=r"(R1),"=r"(R2),"=r"(R3) : "r"(ADDR))
#define LDSM_X4T(R0,R1,R2,R3,ADDR) \
    asm volatile("ldmatrix.sync.aligned.m8n8.x4.trans.shared.b16 {%0,%1,%2,%3}, [%4];" \
                 : "=r"(R0),"=r"(R1),"=r"(R2),"=r"(R3) : "r"(ADDR))
// D += A * B   (m16n8k16, bf16 in, f32 accum)
#define MMA(D,A,B0,B1) \
    asm volatile("mma.sync.aligned.m16n8k16.row.col.f32.bf16.bf16.f32 " \
                 "{%0,%1,%2,%3},{%4,%5,%6,%7},{%8,%9},{%0,%1,%2,%3};" \
                 : "+f"((D)[0]),"+f"((D)[1]),"+f"((D)[2]),"+f"((D)[3]) \
                 : "r"((A)[0]),"r"((A)[1]),"r"((A)[2]),"r"((A)[3]),"r"(B0),"r"(B1))

// ---------------------------------------------------------------------------
// Pre-pass: K,V fp32 -> bf16 hi/lo scratch.  K scaled by log2(e) so the hot
// loop can use ex2.approx directly on the scores.
// ---------------------------------------------------------------------------
__global__ __launch_bounds__(256)
void kv_convert_kernel(const float* __restrict__ k, const float* __restrict__ v)
{
    const float LOG2E = 1.4426950408889634f;
    int i = blockIdx.x * 256 + threadIdx.x;          // float4 index
    float4 kx = reinterpret_cast<const float4*>(k)[i];
    kx.x *= LOG2E; kx.y *= LOG2E; kx.z *= LOG2E; kx.w *= LOG2E;
    float4 vx = reinterpret_cast<const float4*>(v)[i];
    reinterpret_cast<uint2*>(g_khi)[i] = make_uint2(packhi(kx.x, kx.y), packhi(kx.z, kx.w));
    reinterpret_cast<uint2*>(g_klo)[i] = make_uint2(packlo(kx.x, kx.y), packlo(kx.z, kx.w));
    reinterpret_cast<uint2*>(g_vhi)[i] = make_uint2(packhi(vx.x, vx.y), packhi(vx.z, vx.w));
    reinterpret_cast<uint2*>(g_vlo)[i] = make_uint2(packlo(vx.x, vx.y), packlo(vx.z, vx.w));
}

// ---------------------------------------------------------------------------
// Attention kernel
// ---------------------------------------------------------------------------
__global__ __launch_bounds__(NTHREADS, 3)
void attn_mma_kernel(const float* __restrict__ q,
                     float* __restrict__ out)
{
    __shared__ __align__(1024) char smem[SMEM_BYTES];
    const uint32_t sb = smem_u32(smem);
    const int tid  = threadIdx.x;
    const int w    = tid >> 5;                // warp 0..3
    const int lane = tid & 31;
    const int b     = blockIdx.y;
    const int qbase = blockIdx.x * QT;
    const int wr0   = w * 16;                 // this warp's q-row base in tile

    const size_t kvbase = (size_t)b * SEQ * DIM;   // element offset of this batch

    const __nv_bfloat16* g_arr[4] = { g_khi, g_klo, g_vhi, g_vlo };

    // ---- kick off DMA of tile 0 into buf0 ----
    {
#pragma unroll
        for (int i = 0; i < 16; i++) {
            int arr = i >> 2, rc = (i & 3) * NTHREADS + tid;
            int row = rc >> 3, c16 = rc & 7;
            const char* src = (const char*)(g_arr[arr] + kvbase + row * DIM) + c16 * 16;
            CP_ASYNC16(sb + arr * 8192 + swa(row, c16), src);
        }
        CP_COMMIT();
    }

    // ---- Prologue: stage Q (64x64 f32 -> bf16 hi/lo) into buf1 region ----
    {
        const float* qp = q + ((size_t)b * SEQ + qbase) * DIM;
#pragma unroll
        for (int i = 0; i < (QT * DIM / 4) / NTHREADS; i++) {   // 8 iters
            int idx = i * NTHREADS + tid;
            int row = idx >> 4, f4 = idx & 15;
            float4 x = reinterpret_cast<const float4*>(qp + row * DIM)[f4];
            uint32_t off = swa(row, f4 >> 1) + (f4 & 1) * 8;
            *reinterpret_cast<uint2*>(smem + BUF_STRIDE + off) =
                make_uint2(packhi(x.x, x.y), packhi(x.z, x.w));
            *reinterpret_cast<uint2*>(smem + BUF_STRIDE + 8192 + off) =
                make_uint2(packlo(x.x, x.y), packlo(x.z, x.w));
        }
    }
    __syncthreads();

    // Q fragments (A of m16n8k16): 4 k-chunks of 16, hi and lo
    uint32_t qh[4][4], ql[4][4];
    {
        int arow = wr0 + (lane & 7) + ((lane >> 3) & 1) * 8;
#pragma unroll
        for (int kc = 0; kc < 4; kc++) {
            uint32_t off = swa(arow, kc * 2 + (lane >> 4));
            LDSM_X4(qh[kc][0], qh[kc][1], qh[kc][2], qh[kc][3], sb + BUF_STRIDE + off);
            LDSM_X4(ql[kc][0], ql[kc][1], ql[kc][2], ql[kc][3], sb + BUF_STRIDE + 8192 + off);
        }
    }
    __syncthreads();   // buf1 free for tile-1 prefetch after this

    float oacc[8][4];
#pragma unroll
    for (int nt = 0; nt < 8; nt++)
#pragma unroll
        for (int i = 0; i < 4; i++) oacc[nt][i] = 0.0f;
    float ls0 = 0.0f, ls1 = 0.0f;

    // lane mapping for x4 B-operand ldmatrix
    const int m8 = lane >> 3;     // which 8x8 matrix this lane addresses
    const int r8 = lane & 7;

    for (int t = 0; t < NTILES; t++) {
        const uint32_t bufb = sb + (uint32_t)(t & 1) * BUF_STRIDE;

        // ---- prefetch tile t+1 into the other buffer; wait for tile t ----
        if (t + 1 < NTILES) {
            const size_t toff = kvbase + (size_t)(t + 1) * KT * DIM;
            const uint32_t nb = sb + (uint32_t)((t + 1) & 1) * BUF_STRIDE;
#pragma unroll
            for (int i = 0; i < 16; i++) {
                int arr = i >> 2, rc = (i & 3) * NTHREADS + tid;
                int row = rc >> 3, c16 = rc & 7;
                const char* src = (const char*)(g_arr[arr] + toff + row * DIM) + c16 * 16;
                CP_ASYNC16(nb + arr * 8192 + swa(row, c16), src);
            }
            CP_COMMIT();
            CP_WAIT1();          // oldest group (tile t) complete
        } else {
            CP_WAIT0();
        }
        __syncthreads();

        // ---- MMA1: S[16,64] = Qhi.Khi^T + Qhi.Klo^T + Qlo.Khi^T ----
        // (scores are already in log2 units: K pre-scaled by log2e)
        float sacc[8][4];
#pragma unroll
        for (int nt = 0; nt < 8; nt++)
#pragma unroll
            for (int i = 0; i < 4; i++) sacc[nt][i] = 0.0f;

#pragma unroll
        for (int half = 0; half < 2; half++) {
#pragma unroll
            for (int kc = 0; kc < 4; kc++) {
#pragma unroll
                for (int ntl = 0; ntl < 2; ntl++) {
                    int ntp = half * 2 + ntl;
                    int krow  = (ntp * 2 + (m8 >> 1)) * 8 + r8;
                    uint32_t off = swa(krow, kc * 2 + (m8 & 1));
                    uint32_t bh0, bh1, bh2, bh3, bl0, bl1, bl2, bl3;
                    LDSM_X4(bh0, bh1, bh2, bh3, bufb + T_KHI + off);
                    LDSM_X4(bl0, bl1, bl2, bl3, bufb + T_KLO + off);
                    MMA(sacc[2*ntp],   qh[kc], bh0, bh1);
                    MMA(sacc[2*ntp+1], qh[kc], bh2, bh3);
                    MMA(sacc[2*ntp],   qh[kc], bl0, bl1);
                    MMA(sacc[2*ntp+1], qh[kc], bl2, bl3);
                    MMA(sacc[2*ntp],   ql[kc], bh0, bh1);
                    MMA(sacc[2*ntp+1], ql[kc], bh2, bh3);
                }
            }
        }

        // ---- per key-half: exp(S) -> P fragments, then MMA2 on that half.
        //      exp of half h+1 issues while MMA2 of half h executes on tensor.
#pragma unroll
        for (int half = 0; half < 2; half++) {
            uint32_t ph[2][4], pl[2][4];
#pragma unroll
            for (int ntl = 0; ntl < 4; ntl++) {
                int nt = half * 4 + ntl;
                float p0 = ex2f(sacc[nt][0]);
                float p1 = ex2f(sacc[nt][1]);
                float p2 = ex2f(sacc[nt][2]);
                float p3 = ex2f(sacc[nt][3]);
                ls0 += p0 + p1;
                ls1 += p2 + p3;
                // truncation split: hi = top 16 bits, lo = exact fp32 residual
                uint32_t b0 = __float_as_uint(p0), b1 = __float_as_uint(p1);
                uint32_t b2 = __float_as_uint(p2), b3 = __float_as_uint(p3);
                float l0 = p0 - __uint_as_float(b0 & 0xffff0000u);
                float l1 = p1 - __uint_as_float(b1 & 0xffff0000u);
                float l2 = p2 - __uint_as_float(b2 & 0xffff0000u);
                float l3 = p3 - __uint_as_float(b3 & 0xffff0000u);
                int kcl = ntl >> 1, h = (ntl & 1) * 2;
                ph[kcl][h]     = __byte_perm(b0, b1, 0x7632);
                ph[kcl][h + 1] = __byte_perm(b2, b3, 0x7632);
                pl[kcl][h]     = packhi(l0, l1);
                pl[kcl][h + 1] = packhi(l2, l3);
            }

            // MMA2 for key-chunks of this half: O += Phi.Vhi + Phi.Vlo + Plo.Vhi
#pragma unroll
            for (int kcl = 0; kcl < 2; kcl++) {
                int kcg = half * 2 + kcl;
#pragma unroll
                for (int ntp = 0; ntp < 4; ntp++) {
                    int vrow = kcg * 16 + (m8 & 1) * 8 + r8;
                    uint32_t off = swa(vrow, ntp * 2 + (m8 >> 1));
                    uint32_t bh0, bh1, bh2, bh3, bl0, bl1, bl2, bl3;
                    LDSM_X4T(bh0, bh1, bh2, bh3, bufb + T_VHI + off);
                    LDSM_X4T(bl0, bl1, bl2, bl3, bufb + T_VLO + off);
                    MMA(oacc[2*ntp],   ph[kcl], bh0, bh1);
                    MMA(oacc[2*ntp+1], ph[kcl], bh2, bh3);
                    MMA(oacc[2*ntp],   ph[kcl], bl0, bl1);
                    MMA(oacc[2*ntp+1], ph[kcl], bl2, bl3);
                    MMA(oacc[2*ntp],   pl[kcl], bh0, bh1);
                    MMA(oacc[2*ntp+1], pl[kcl], bh2, bh3);
                }
            }
        }
        __syncthreads();   // tile t reads done -> buffer reusable next iter
    }

    // ---- row sums: reduce over the 4 lanes of each row group ----
    ls0 += __shfl_xor_sync(0xffffffffu, ls0, 1);
    ls0 += __shfl_xor_sync(0xffffffffu, ls0, 2);
    ls1 += __shfl_xor_sync(0xffffffffu, ls1, 1);
    ls1 += __shfl_xor_sync(0xffffffffu, ls1, 2);
    const float inv0 = 1.0f / ls0;
    const float inv1 = 1.0f / ls1;

    // ---- normalize + store ----
    {
        const int r = lane >> 2, c = lane & 3;
        float* op0 = out + ((size_t)b * SEQ + qbase + wr0 + r) * DIM;
        float* op1 = op0 + 8 * DIM;
#pragma unroll
        for (int nt = 0; nt < 8; nt++) {
            float2 t0 = make_float2(oacc[nt][0] * inv0, oacc[nt][1] * inv0);
            float2 t1 = make_float2(oacc[nt][2] * inv1, oacc[nt][3] * inv1);
            *reinterpret_cast<float2*>(op0 + nt * 8 + 2 * c) = t0;
            *reinterpret_cast<float2*>(op1 + nt * 8 + 2 * c) = t1;
        }
    }
}

extern "C" void kernel_launch(void* const* d_in, const int* in_sizes, int n_in,
                              void* d_out, int out_size)
{
    const float* q = (const float*)d_in[0];
    const float* k = (const float*)d_in[1];
    const float* v = (const float*)d_in[2];
    float* out = (float*)d_out;

    kv_convert_kernel<<<KV_ELEMS / 4 / 256, 256>>>(k, v);

    dim3 grid(SEQ / QT, BATCH);
    attn_mma_kernel<<<grid, NTHREADS>>>(q, out);
}

// round 11
// speedup vs baseline: 1.7084x; 1.1663x over previous
#include <cuda_runtime.h>
#include <cuda_bf16.h>
#include <cstdint>

// ============================================================================
// multimodal_attention via mma.sync (HMMA bf16 hi/lo split) on sm_103
// out[b,q,:] = softmax_k(Q.K^T) @ V       B=32, S=2048, D=64, fp32
//
// R10: MMA2 reduced to 2 terms (Phi.Vhi + Phi.Vlo).  The row-sum is computed
//      from the SAME truncated phi as the numerator, so the dominant-key
//      truncation error cancels in the softmax normalization.  MMA1 keeps
//      3 terms (pre-exp score errors don't cancel).  ls chains split 4-way.
// ============================================================================

#define BATCH 32
#define SEQ   2048
#define DIM   64
#define QT    64             // q rows per CTA
#define KT    64             // keys per tile
#define NTILES (SEQ / KT)    // 32
#define NTHREADS 128

#define KV_ELEMS (BATCH * SEQ * DIM)     // 4,194,304

// preconverted K/V scratch (32 MB total); K pre-scaled by log2(e)
__device__ __nv_bfloat16 g_khi[KV_ELEMS];
__device__ __nv_bfloat16 g_klo[KV_ELEMS];
__device__ __nv_bfloat16 g_vhi[KV_ELEMS];
__device__ __nv_bfloat16 g_vlo[KV_ELEMS];

// smem: double buffer, each buf = {KHI,KLO,VHI,VLO} 8KB tiles = 32KB
#define BUF_STRIDE 32768
#define T_KHI 0
#define T_KLO 8192
#define T_VHI 16384
#define T_VLO 24576
#define SMEM_BYTES (2 * BUF_STRIDE)      // 64KB static

__device__ __forceinline__ uint32_t smem_u32(const void* p) {
    uint32_t a;
    asm("{ .reg .u64 t; cvta.to.shared.u64 t, %1; cvt.u32.u64 %0, t; }" : "=r"(a) : "l"(p));
    return a;
}
// 128B rows; xor-swizzle 16B chunks by row&7 -> conflict-free ldmatrix
__device__ __forceinline__ uint32_t swa(int row, int col16) {
    return (uint32_t)(row * 128 + ((col16 ^ (row & 7)) << 4));
}
__device__ __forceinline__ uint32_t packhi(float a, float b) {
    __nv_bfloat162 t = __floats2bfloat162_rn(a, b);
    return *reinterpret_cast<uint32_t*>(&t);
}
__device__ __forceinline__ uint32_t packlo(float a, float b) {
    float ah = __bfloat162float(__float2bfloat16_rn(a));
    float bh = __bfloat162float(__float2bfloat16_rn(b));
    __nv_bfloat162 t = __floats2bfloat162_rn(a - ah, b - bh);
    return *reinterpret_cast<uint32_t*>(&t);
}
__device__ __forceinline__ float ex2f(float x) {
    float r;
    asm("ex2.approx.ftz.f32 %0, %1;" : "=f"(r) : "f"(x));
    return r;
}

#define CP_ASYNC16(SM, GM) \
    asm volatile("cp.async.cg.shared.global [%0], [%1], 16;" :: "r"(SM), "l"(GM) : "memory")
#define CP_COMMIT()  asm volatile("cp.async.commit_group;" ::: "memory")
#define CP_WAIT0()   asm volatile("cp.async.wait_group 0;" ::: "memory")
#define CP_WAIT1()   asm volatile("cp.async.wait_group 1;" ::: "memory")

#define LDSM_X4(R0,R1,R2,R3,ADDR) \
    asm volatile("ldmatrix.sync.aligned.m8n8.x4.shared.b16 {%0,%1,%2,%3}, [%4];" \
                 : "=r"(R0),"=r"(R1),"=r"(R2),"=r"(R3) : "r"(ADDR))
#define LDSM_X4T(R0,R1,R2,R3,ADDR) \
    asm volatile("ldmatrix.sync.aligned.m8n8.x4.trans.shared.b16 {%0,%1,%2,%3}, [%4];" \
                 : "=r"(R0),"=r"(R1),"=r"(R2),"=r"(R3) : "r"(ADDR))
// D += A * B   (m16n8k16, bf16 in, f32 accum)
#define MMA(D,A,B0,B1) \
    asm volatile("mma.sync.aligned.m16n8k16.row.col.f32.bf16.bf16.f32 " \
                 "{%0,%1,%2,%3},{%4,%5,%6,%7},{%8,%9},{%0,%1,%2,%3};" \
                 : "+f"((D)[0]),"+f"((D)[1]),"+f"((D)[2]),"+f"((D)[3]) \
                 : "r"((A)[0]),"r"((A)[1]),"r"((A)[2]),"r"((A)[3]),"r"(B0),"r"(B1))

// ---------------------------------------------------------------------------
// Pre-pass: K,V fp32 -> bf16 hi/lo scratch.  K scaled by log2(e) so the hot
// loop can use ex2.approx directly on the scores.
// ---------------------------------------------------------------------------
__global__ __launch_bounds__(256)
void kv_convert_kernel(const float* __restrict__ k, const float* __restrict__ v)
{
    const float LOG2E = 1.4426950408889634f;
    int i = blockIdx.x * 256 + threadIdx.x;          // float4 index
    float4 kx = reinterpret_cast<const float4*>(k)[i];
    kx.x *= LOG2E; kx.y *= LOG2E; kx.z *= LOG2E; kx.w *= LOG2E;
    float4 vx = reinterpret_cast<const float4*>(v)[i];
    reinterpret_cast<uint2*>(g_khi)[i] = make_uint2(packhi(kx.x, kx.y), packhi(kx.z, kx.w));
    reinterpret_cast<uint2*>(g_klo)[i] = make_uint2(packlo(kx.x, kx.y), packlo(kx.z, kx.w));
    reinterpret_cast<uint2*>(g_vhi)[i] = make_uint2(packhi(vx.x, vx.y), packhi(vx.z, vx.w));
    reinterpret_cast<uint2*>(g_vlo)[i] = make_uint2(packlo(vx.x, vx.y), packlo(vx.z, vx.w));
}

// ---------------------------------------------------------------------------
// Attention kernel
// ---------------------------------------------------------------------------
__global__ __launch_bounds__(NTHREADS, 3)
void attn_mma_kernel(const float* __restrict__ q,
                     float* __restrict__ out)
{
    __shared__ __align__(1024) char smem[SMEM_BYTES];
    const uint32_t sb = smem_u32(smem);
    const int tid  = threadIdx.x;
    const int w    = tid >> 5;                // warp 0..3
    const int lane = tid & 31;
    const int b     = blockIdx.y;
    const int qbase = blockIdx.x * QT;
    const int wr0   = w * 16;                 // this warp's q-row base in tile

    const size_t kvbase = (size_t)b * SEQ * DIM;   // element offset of this batch

    const __nv_bfloat16* g_arr[4] = { g_khi, g_klo, g_vhi, g_vlo };

    // ---- kick off DMA of tile 0 into buf0 ----
    {
#pragma unroll
        for (int i = 0; i < 16; i++) {
            int arr = i >> 2, rc = (i & 3) * NTHREADS + tid;
            int row = rc >> 3, c16 = rc & 7;
            const char* src = (const char*)(g_arr[arr] + kvbase + row * DIM) + c16 * 16;
            CP_ASYNC16(sb + arr * 8192 + swa(row, c16), src);
        }
        CP_COMMIT();
    }

    // ---- Prologue: stage Q (64x64 f32 -> bf16 hi/lo) into buf1 region ----
    {
        const float* qp = q + ((size_t)b * SEQ + qbase) * DIM;
#pragma unroll
        for (int i = 0; i < (QT * DIM / 4) / NTHREADS; i++) {   // 8 iters
            int idx = i * NTHREADS + tid;
            int row = idx >> 4, f4 = idx & 15;
            float4 x = reinterpret_cast<const float4*>(qp + row * DIM)[f4];
            uint32_t off = swa(row, f4 >> 1) + (f4 & 1) * 8;
            *reinterpret_cast<uint2*>(smem + BUF_STRIDE + off) =
                make_uint2(packhi(x.x, x.y), packhi(x.z, x.w));
            *reinterpret_cast<uint2*>(smem + BUF_STRIDE + 8192 + off) =
                make_uint2(packlo(x.x, x.y), packlo(x.z, x.w));
        }
    }
    __syncthreads();

    // Q fragments (A of m16n8k16): 4 k-chunks of 16, hi and lo
    uint32_t qh[4][4], ql[4][4];
    {
        int arow = wr0 + (lane & 7) + ((lane >> 3) & 1) * 8;
#pragma unroll
        for (int kc = 0; kc < 4; kc++) {
            uint32_t off = swa(arow, kc * 2 + (lane >> 4));
            LDSM_X4(qh[kc][0], qh[kc][1], qh[kc][2], qh[kc][3], sb + BUF_STRIDE + off);
            LDSM_X4(ql[kc][0], ql[kc][1], ql[kc][2], ql[kc][3], sb + BUF_STRIDE + 8192 + off);
        }
    }
    __syncthreads();   // buf1 free for tile-1 prefetch after this

    float oacc[8][4];
#pragma unroll
    for (int nt = 0; nt < 8; nt++)
#pragma unroll
        for (int i = 0; i < 4; i++) oacc[nt][i] = 0.0f;
    // 4-way split row-sum accumulators (rows r / r+8)
    float ls0a = 0.0f, ls0b = 0.0f, ls1a = 0.0f, ls1b = 0.0f;

    // lane mapping for x4 B-operand ldmatrix
    const int m8 = lane >> 3;     // which 8x8 matrix this lane addresses
    const int r8 = lane & 7;

    for (int t = 0; t < NTILES; t++) {
        const uint32_t bufb = sb + (uint32_t)(t & 1) * BUF_STRIDE;

        // ---- prefetch tile t+1 into the other buffer; wait for tile t ----
        if (t + 1 < NTILES) {
            const size_t toff = kvbase + (size_t)(t + 1) * KT * DIM;
            const uint32_t nb = sb + (uint32_t)((t + 1) & 1) * BUF_STRIDE;
#pragma unroll
            for (int i = 0; i < 16; i++) {
                int arr = i >> 2, rc = (i & 3) * NTHREADS + tid;
                int row = rc >> 3, c16 = rc & 7;
                const char* src = (const char*)(g_arr[arr] + toff + row * DIM) + c16 * 16;
                CP_ASYNC16(nb + arr * 8192 + swa(row, c16), src);
            }
            CP_COMMIT();
            CP_WAIT1();          // oldest group (tile t) complete
        } else {
            CP_WAIT0();
        }
        __syncthreads();

        // ---- MMA1: S[16,64] = Qhi.Khi^T + Qhi.Klo^T + Qlo.Khi^T ----
        // (scores are already in log2 units: K pre-scaled by log2e)
        float sacc[8][4];
#pragma unroll
        for (int nt = 0; nt < 8; nt++)
#pragma unroll
            for (int i = 0; i < 4; i++) sacc[nt][i] = 0.0f;

#pragma unroll
        for (int half = 0; half < 2; half++) {
#pragma unroll
            for (int kc = 0; kc < 4; kc++) {
#pragma unroll
                for (int ntl = 0; ntl < 2; ntl++) {
                    int ntp = half * 2 + ntl;
                    int krow  = (ntp * 2 + (m8 >> 1)) * 8 + r8;
                    uint32_t off = swa(krow, kc * 2 + (m8 & 1));
                    uint32_t bh0, bh1, bh2, bh3, bl0, bl1, bl2, bl3;
                    LDSM_X4(bh0, bh1, bh2, bh3, bufb + T_KHI + off);
                    LDSM_X4(bl0, bl1, bl2, bl3, bufb + T_KLO + off);
                    MMA(sacc[2*ntp],   qh[kc], bh0, bh1);
                    MMA(sacc[2*ntp+1], qh[kc], bh2, bh3);
                    MMA(sacc[2*ntp],   qh[kc], bl0, bl1);
                    MMA(sacc[2*ntp+1], qh[kc], bl2, bl3);
                    MMA(sacc[2*ntp],   ql[kc], bh0, bh1);
                    MMA(sacc[2*ntp+1], ql[kc], bh2, bh3);
                }
            }
        }

        // ---- per key-half: exp(S) -> truncated Phi fragments, then MMA2.
        //      Row-sum uses the SAME truncated phi -> dominant-key truncation
        //      error cancels in the final normalization.
#pragma unroll
        for (int half = 0; half < 2; half++) {
            uint32_t ph[2][4];
#pragma unroll
            for (int ntl = 0; ntl < 4; ntl++) {
                int nt = half * 4 + ntl;
                float p0 = ex2f(sacc[nt][0]);
                float p1 = ex2f(sacc[nt][1]);
                float p2 = ex2f(sacc[nt][2]);
                float p3 = ex2f(sacc[nt][3]);
                uint32_t b0 = __float_as_uint(p0), b1 = __float_as_uint(p1);
                uint32_t b2 = __float_as_uint(p2), b3 = __float_as_uint(p3);
                // truncated phi values (what the MMA actually multiplies)
                float h0 = __uint_as_float(b0 & 0xffff0000u);
                float h1 = __uint_as_float(b1 & 0xffff0000u);
                float h2 = __uint_as_float(b2 & 0xffff0000u);
                float h3 = __uint_as_float(b3 & 0xffff0000u);
                ls0a += h0; ls0b += h1;
                ls1a += h2; ls1b += h3;
                int kcl = ntl >> 1, h = (ntl & 1) * 2;
                ph[kcl][h]     = __byte_perm(b0, b1, 0x7632);
                ph[kcl][h + 1] = __byte_perm(b2, b3, 0x7632);
            }

            // MMA2 for key-chunks of this half: O += Phi.Vhi + Phi.Vlo
#pragma unroll
            for (int kcl = 0; kcl < 2; kcl++) {
                int kcg = half * 2 + kcl;
#pragma unroll
                for (int ntp = 0; ntp < 4; ntp++) {
                    int vrow = kcg * 16 + (m8 & 1) * 8 + r8;
                    uint32_t off = swa(vrow, ntp * 2 + (m8 >> 1));
                    uint32_t bh0, bh1, bh2, bh3, bl0, bl1, bl2, bl3;
                    LDSM_X4T(bh0, bh1, bh2, bh3, bufb + T_VHI + off);
                    LDSM_X4T(bl0, bl1, bl2, bl3, bufb + T_VLO + off);
                    MMA(oacc[2*ntp],   ph[kcl], bh0, bh1);
                    MMA(oacc[2*ntp+1], ph[kcl], bh2, bh3);
                    MMA(oacc[2*ntp],   ph[kcl], bl0, bl1);
                    MMA(oacc[2*ntp+1], ph[kcl], bl2, bl3);
                }
            }
        }
        __syncthreads();   // tile t reads done -> buffer reusable next iter
    }

    // ---- row sums: merge partials, reduce over the 4 lanes of each row group
    float ls0 = (ls0a + ls0b);
    float ls1 = (ls1a + ls1b);
    ls0 += __shfl_xor_sync(0xffffffffu, ls0, 1);
    ls0 += __shfl_xor_sync(0xffffffffu, ls0, 2);
    ls1 += __shfl_xor_sync(0xffffffffu, ls1, 1);
    ls1 += __shfl_xor_sync(0xffffffffu, ls1, 2);
    const float inv0 = 1.0f / ls0;
    const float inv1 = 1.0f / ls1;

    // ---- normalize + store ----
    {
        const int r = lane >> 2, c = lane & 3;
        float* op0 = out + ((size_t)b * SEQ + qbase + wr0 + r) * DIM;
        float* op1 = op0 + 8 * DIM;
#pragma unroll
        for (int nt = 0; nt < 8; nt++) {
            float2 t0 = make_float2(oacc[nt][0] * inv0, oacc[nt][1] * inv0);
            float2 t1 = make_float2(oacc[nt][2] * inv1, oacc[nt][3] * inv1);
            *reinterpret_cast<float2*>(op0 + nt * 8 + 2 * c) = t0;
            *reinterpret_cast<float2*>(op1 + nt * 8 + 2 * c) = t1;
        }
    }
}

extern "C" void kernel_launch(void* const* d_in, const int* in_sizes, int n_in,
                              void* d_out, int out_size)
{
    const float* q = (const float*)d_in[0];
    const float* k = (const float*)d_in[1];
    const float* v = (const float*)d_in[2];
    float* out = (float*)d_out;

    kv_convert_kernel<<<KV_ELEMS / 4 / 256, 256>>>(k, v);

    dim3 grid(SEQ / QT, BATCH);
    attn_mma_kernel<<<grid, NTHREADS>>>(q, out);
}

// round 12
// speedup vs baseline: 1.7267x; 1.0107x over previous
#include <cuda_runtime.h>
#include <cuda_bf16.h>
#include <cstdint>

// ============================================================================
// multimodal_attention via mma.sync (HMMA bf16 hi/lo split) on sm_103
// out[b,q,:] = softmax_k(Q.K^T) @ V       B=32, S=2048, D=64, fp32
//
// R11: phi quantized with round-to-nearest bf16 (unbiased, +-2^-10) instead of
//      truncation (biased, -2^-9).  Row-sum computed from the SAME packed
//      rn-rounded word (unpack via shift/mask), preserving the normalization
//      cancellation.  MMA structure unchanged: MMA1 3-term, MMA2 2-term.
// ============================================================================

#define BATCH 32
#define SEQ   2048
#define DIM   64
#define QT    64             // q rows per CTA
#define KT    64             // keys per tile
#define NTILES (SEQ / KT)    // 32
#define NTHREADS 128

#define KV_ELEMS (BATCH * SEQ * DIM)     // 4,194,304

// preconverted K/V scratch (32 MB total); K pre-scaled by log2(e)
__device__ __nv_bfloat16 g_khi[KV_ELEMS];
__device__ __nv_bfloat16 g_klo[KV_ELEMS];
__device__ __nv_bfloat16 g_vhi[KV_ELEMS];
__device__ __nv_bfloat16 g_vlo[KV_ELEMS];

// smem: double buffer, each buf = {KHI,KLO,VHI,VLO} 8KB tiles = 32KB
#define BUF_STRIDE 32768
#define T_KHI 0
#define T_KLO 8192
#define T_VHI 16384
#define T_VLO 24576
#define SMEM_BYTES (2 * BUF_STRIDE)      // 64KB static

__device__ __forceinline__ uint32_t smem_u32(const void* p) {
    uint32_t a;
    asm("{ .reg .u64 t; cvta.to.shared.u64 t, %1; cvt.u32.u64 %0, t; }" : "=r"(a) : "l"(p));
    return a;
}
// 128B rows; xor-swizzle 16B chunks by row&7 -> conflict-free ldmatrix
__device__ __forceinline__ uint32_t swa(int row, int col16) {
    return (uint32_t)(row * 128 + ((col16 ^ (row & 7)) << 4));
}
__device__ __forceinline__ uint32_t packhi(float a, float b) {
    __nv_bfloat162 t = __floats2bfloat162_rn(a, b);
    return *reinterpret_cast<uint32_t*>(&t);
}
__device__ __forceinline__ uint32_t packlo(float a, float b) {
    float ah = __bfloat162float(__float2bfloat16_rn(a));
    float bh = __bfloat162float(__float2bfloat16_rn(b));
    __nv_bfloat162 t = __floats2bfloat162_rn(a - ah, b - bh);
    return *reinterpret_cast<uint32_t*>(&t);
}
__device__ __forceinline__ float ex2f(float x) {
    float r;
    asm("ex2.approx.ftz.f32 %0, %1;" : "=f"(r) : "f"(x));
    return r;
}

#define CP_ASYNC16(SM, GM) \
    asm volatile("cp.async.cg.shared.global [%0], [%1], 16;" :: "r"(SM), "l"(GM) : "memory")
#define CP_COMMIT()  asm volatile("cp.async.commit_group;" ::: "memory")
#define CP_WAIT0()   asm volatile("cp.async.wait_group 0;" ::: "memory")
#define CP_WAIT1()   asm volatile("cp.async.wait_group 1;" ::: "memory")

#define LDSM_X4(R0,R1,R2,R3,ADDR) \
    asm volatile("ldmatrix.sync.aligned.m8n8.x4.shared.b16 {%0,%1,%2,%3}, [%4];" \
                 : "=r"(R0),"=r"(R1),"=r"(R2),"=r"(R3) : "r"(ADDR))
#define LDSM_X4T(R0,R1,R2,R3,ADDR) \
    asm volatile("ldmatrix.sync.aligned.m8n8.x4.trans.shared.b16 {%0,%1,%2,%3}, [%4];" \
                 : "=r"(R0),"=r"(R1),"=r"(R2),"=r"(R3) : "r"(ADDR))
// D += A * B   (m16n8k16, bf16 in, f32 accum)
#define MMA(D,A,B0,B1) \
    asm volatile("mma.sync.aligned.m16n8k16.row.col.f32.bf16.bf16.f32 " \
                 "{%0,%1,%2,%3},{%4,%5,%6,%7},{%8,%9},{%0,%1,%2,%3};" \
                 : "+f"((D)[0]),"+f"((D)[1]),"+f"((D)[2]),"+f"((D)[3]) \
                 : "r"((A)[0]),"r"((A)[1]),"r"((A)[2]),"r"((A)[3]),"r"(B0),"r"(B1))

// ---------------------------------------------------------------------------
// Pre-pass: K,V fp32 -> bf16 hi/lo scratch.  K scaled by log2(e) so the hot
// loop can use ex2.approx directly on the scores.
// ---------------------------------------------------------------------------
__global__ __launch_bounds__(256)
void kv_convert_kernel(const float* __restrict__ k, const float* __restrict__ v)
{
    const float LOG2E = 1.4426950408889634f;
    int i = blockIdx.x * 256 + threadIdx.x;          // float4 index
    float4 kx = reinterpret_cast<const float4*>(k)[i];
    kx.x *= LOG2E; kx.y *= LOG2E; kx.z *= LOG2E; kx.w *= LOG2E;
    float4 vx = reinterpret_cast<const float4*>(v)[i];
    reinterpret_cast<uint2*>(g_khi)[i] = make_uint2(packhi(kx.x, kx.y), packhi(kx.z, kx.w));
    reinterpret_cast<uint2*>(g_klo)[i] = make_uint2(packlo(kx.x, kx.y), packlo(kx.z, kx.w));
    reinterpret_cast<uint2*>(g_vhi)[i] = make_uint2(packhi(vx.x, vx.y), packhi(vx.z, vx.w));
    reinterpret_cast<uint2*>(g_vlo)[i] = make_uint2(packlo(vx.x, vx.y), packlo(vx.z, vx.w));
}

// ---------------------------------------------------------------------------
// Attention kernel
// ---------------------------------------------------------------------------
__global__ __launch_bounds__(NTHREADS, 3)
void attn_mma_kernel(const float* __restrict__ q,
                     float* __restrict__ out)
{
    __shared__ __align__(1024) char smem[SMEM_BYTES];
    const uint32_t sb = smem_u32(smem);
    const int tid  = threadIdx.x;
    const int w    = tid >> 5;                // warp 0..3
    const int lane = tid & 31;
    const int b     = blockIdx.y;
    const int qbase = blockIdx.x * QT;
    const int wr0   = w * 16;                 // this warp's q-row base in tile

    const size_t kvbase = (size_t)b * SEQ * DIM;   // element offset of this batch

    const __nv_bfloat16* g_arr[4] = { g_khi, g_klo, g_vhi, g_vlo };

    // ---- kick off DMA of tile 0 into buf0 ----
    {
#pragma unroll
        for (int i = 0; i < 16; i++) {
            int arr = i >> 2, rc = (i & 3) * NTHREADS + tid;
            int row = rc >> 3, c16 = rc & 7;
            const char* src = (const char*)(g_arr[arr] + kvbase + row * DIM) + c16 * 16;
            CP_ASYNC16(sb + arr * 8192 + swa(row, c16), src);
        }
        CP_COMMIT();
    }

    // ---- Prologue: stage Q (64x64 f32 -> bf16 hi/lo) into buf1 region ----
    {
        const float* qp = q + ((size_t)b * SEQ + qbase) * DIM;
#pragma unroll
        for (int i = 0; i < (QT * DIM / 4) / NTHREADS; i++) {   // 8 iters
            int idx = i * NTHREADS + tid;
            int row = idx >> 4, f4 = idx & 15;
            float4 x = reinterpret_cast<const float4*>(qp + row * DIM)[f4];
            uint32_t off = swa(row, f4 >> 1) + (f4 & 1) * 8;
            *reinterpret_cast<uint2*>(smem + BUF_STRIDE + off) =
                make_uint2(packhi(x.x, x.y), packhi(x.z, x.w));
            *reinterpret_cast<uint2*>(smem + BUF_STRIDE + 8192 + off) =
                make_uint2(packlo(x.x, x.y), packlo(x.z, x.w));
        }
    }
    __syncthreads();

    // Q fragments (A of m16n8k16): 4 k-chunks of 16, hi and lo
    uint32_t qh[4][4], ql[4][4];
    {
        int arow = wr0 + (lane & 7) + ((lane >> 3) & 1) * 8;
#pragma unroll
        for (int kc = 0; kc < 4; kc++) {
            uint32_t off = swa(arow, kc * 2 + (lane >> 4));
            LDSM_X4(qh[kc][0], qh[kc][1], qh[kc][2], qh[kc][3], sb + BUF_STRIDE + off);
            LDSM_X4(ql[kc][0], ql[kc][1], ql[kc][2], ql[kc][3], sb + BUF_STRIDE + 8192 + off);
        }
    }
    __syncthreads();   // buf1 free for tile-1 prefetch after this

    float oacc[8][4];
#pragma unroll
    for (int nt = 0; nt < 8; nt++)
#pragma unroll
        for (int i = 0; i < 4; i++) oacc[nt][i] = 0.0f;
    // 4-way split row-sum accumulators (rows r / r+8)
    float ls0a = 0.0f, ls0b = 0.0f, ls1a = 0.0f, ls1b = 0.0f;

    // lane mapping for x4 B-operand ldmatrix
    const int m8 = lane >> 3;     // which 8x8 matrix this lane addresses
    const int r8 = lane & 7;

    for (int t = 0; t < NTILES; t++) {
        const uint32_t bufb = sb + (uint32_t)(t & 1) * BUF_STRIDE;

        // ---- prefetch tile t+1 into the other buffer; wait for tile t ----
        if (t + 1 < NTILES) {
            const size_t toff = kvbase + (size_t)(t + 1) * KT * DIM;
            const uint32_t nb = sb + (uint32_t)((t + 1) & 1) * BUF_STRIDE;
#pragma unroll
            for (int i = 0; i < 16; i++) {
                int arr = i >> 2, rc = (i & 3) * NTHREADS + tid;
                int row = rc >> 3, c16 = rc & 7;
                const char* src = (const char*)(g_arr[arr] + toff + row * DIM) + c16 * 16;
                CP_ASYNC16(nb + arr * 8192 + swa(row, c16), src);
            }
            CP_COMMIT();
            CP_WAIT1();          // oldest group (tile t) complete
        } else {
            CP_WAIT0();
        }
        __syncthreads();

        // ---- MMA1: S[16,64] = Qhi.Khi^T + Qhi.Klo^T + Qlo.Khi^T ----
        // (scores are already in log2 units: K pre-scaled by log2e)
        float sacc[8][4];
#pragma unroll
        for (int nt = 0; nt < 8; nt++)
#pragma unroll
            for (int i = 0; i < 4; i++) sacc[nt][i] = 0.0f;

#pragma unroll
        for (int half = 0; half < 2; half++) {
#pragma unroll
            for (int kc = 0; kc < 4; kc++) {
#pragma unroll
                for (int ntl = 0; ntl < 2; ntl++) {
                    int ntp = half * 2 + ntl;
                    int krow  = (ntp * 2 + (m8 >> 1)) * 8 + r8;
                    uint32_t off = swa(krow, kc * 2 + (m8 & 1));
                    uint32_t bh0, bh1, bh2, bh3, bl0, bl1, bl2, bl3;
                    LDSM_X4(bh0, bh1, bh2, bh3, bufb + T_KHI + off);
                    LDSM_X4(bl0, bl1, bl2, bl3, bufb + T_KLO + off);
                    MMA(sacc[2*ntp],   qh[kc], bh0, bh1);
                    MMA(sacc[2*ntp+1], qh[kc], bh2, bh3);
                    MMA(sacc[2*ntp],   qh[kc], bl0, bl1);
                    MMA(sacc[2*ntp+1], qh[kc], bl2, bl3);
                    MMA(sacc[2*ntp],   ql[kc], bh0, bh1);
                    MMA(sacc[2*ntp+1], ql[kc], bh2, bh3);
                }
            }
        }

        // ---- per key-half: exp(S) -> rn-rounded Phi fragments, then MMA2.
        //      Row-sum unpacks the SAME packed phi word -> normalization
        //      cancellation is exact w.r.t. what the MMA multiplies.
#pragma unroll
        for (int half = 0; half < 2; half++) {
            uint32_t ph[2][4];
#pragma unroll
            for (int ntl = 0; ntl < 4; ntl++) {
                int nt = half * 4 + ntl;
                float p0 = ex2f(sacc[nt][0]);
                float p1 = ex2f(sacc[nt][1]);
                float p2 = ex2f(sacc[nt][2]);
                float p3 = ex2f(sacc[nt][3]);
                uint32_t w01 = packhi(p0, p1);    // rn-rounded bf16x2 (p0 lo, p1 hi)
                uint32_t w23 = packhi(p2, p3);
                // exact values seen by the MMA:
                ls0a += __uint_as_float(w01 << 16);
                ls0b += __uint_as_float(w01 & 0xffff0000u);
                ls1a += __uint_as_float(w23 << 16);
                ls1b += __uint_as_float(w23 & 0xffff0000u);
                int kcl = ntl >> 1, h = (ntl & 1) * 2;
                ph[kcl][h]     = w01;
                ph[kcl][h + 1] = w23;
            }

            // MMA2 for key-chunks of this half: O += Phi.Vhi + Phi.Vlo
#pragma unroll
            for (int kcl = 0; kcl < 2; kcl++) {
                int kcg = half * 2 + kcl;
#pragma unroll
                for (int ntp = 0; ntp < 4; ntp++) {
                    int vrow = kcg * 16 + (m8 & 1) * 8 + r8;
                    uint32_t off = swa(vrow, ntp * 2 + (m8 >> 1));
                    uint32_t bh0, bh1, bh2, bh3, bl0, bl1, bl2, bl3;
                    LDSM_X4T(bh0, bh1, bh2, bh3, bufb + T_VHI + off);
                    LDSM_X4T(bl0, bl1, bl2, bl3, bufb + T_VLO + off);
                    MMA(oacc[2*ntp],   ph[kcl], bh0, bh1);
                    MMA(oacc[2*ntp+1], ph[kcl], bh2, bh3);
                    MMA(oacc[2*ntp],   ph[kcl], bl0, bl1);
                    MMA(oacc[2*ntp+1], ph[kcl], bl2, bl3);
                }
            }
        }
        __syncthreads();   // tile t reads done -> buffer reusable next iter
    }

    // ---- row sums: merge partials, reduce over the 4 lanes of each row group
    float ls0 = (ls0a + ls0b);
    float ls1 = (ls1a + ls1b);
    ls0 += __shfl_xor_sync(0xffffffffu, ls0, 1);
    ls0 += __shfl_xor_sync(0xffffffffu, ls0, 2);
    ls1 += __shfl_xor_sync(0xffffffffu, ls1, 1);
    ls1 += __shfl_xor_sync(0xffffffffu, ls1, 2);
    const float inv0 = 1.0f / ls0;
    const float inv1 = 1.0f / ls1;

    // ---- normalize + store ----
    {
        const int r = lane >> 2, c = lane & 3;
        float* op0 = out + ((size_t)b * SEQ + qbase + wr0 + r) * DIM;
        float* op1 = op0 + 8 * DIM;
#pragma unroll
        for (int nt = 0; nt < 8; nt++) {
            float2 t0 = make_float2(oacc[nt][0] * inv0, oacc[nt][1] * inv0);
            float2 t1 = make_float2(oacc[nt][2] * inv1, oacc[nt][3] * inv1);
            *reinterpret_cast<float2*>(op0 + nt * 8 + 2 * c) = t0;
            *reinterpret_cast<float2*>(op1 + nt * 8 + 2 * c) = t1;
        }
    }
}

extern "C" void kernel_launch(void* const* d_in, const int* in_sizes, int n_in,
                              void* d_out, int out_size)
{
    const float* q = (const float*)d_in[0];
    const float* k = (const float*)d_in[1];
    const float* v = (const float*)d_in[2];
    float* out = (float*)d_out;

    kv_convert_kernel<<<KV_ELEMS / 4 / 256, 256>>>(k, v);

    dim3 grid(SEQ / QT, BATCH);
    attn_mma_kernel<<<grid, NTHREADS>>>(q, out);
}

// round 14
// speedup vs baseline: 1.7475x; 1.0120x over previous
#include <cuda_runtime.h>
#include <cuda_bf16.h>
#include <cstdint>

// ============================================================================
// multimodal_attention via mma.sync (HMMA bf16 hi/lo split) on sm_103
// out[b,q,:] = softmax_k(Q.K^T) @ V       B=32, S=2048, D=64, fp32
//
// R13: R12 with the 4x row-sum bug fixed.  The ones-MMA writes the COMPLETE
//      row sum into every column of lsacc, so no cross-lane shfl reduction is
//      needed (R12 erroneously kept it -> denominator 4x -> rel_err 0.75).
// ============================================================================

#define BATCH 32
#define SEQ   2048
#define DIM   64
#define QT    64             // q rows per CTA
#define KT    64             // keys per tile
#define NTILES (SEQ / KT)    // 32
#define NTHREADS 128

#define KV_ELEMS (BATCH * SEQ * DIM)     // 4,194,304

// preconverted K/V scratch (32 MB total); K pre-scaled by log2(e)
__device__ __nv_bfloat16 g_khi[KV_ELEMS];
__device__ __nv_bfloat16 g_klo[KV_ELEMS];
__device__ __nv_bfloat16 g_vhi[KV_ELEMS];
__device__ __nv_bfloat16 g_vlo[KV_ELEMS];

// smem: double buffer, each buf = {KHI,KLO,VHI,VLO} 8KB tiles = 32KB
#define BUF_STRIDE 32768
#define T_KHI 0
#define T_KLO 8192
#define T_VHI 16384
#define T_VLO 24576
#define SMEM_BYTES (2 * BUF_STRIDE)      // 64KB static

__device__ __forceinline__ uint32_t smem_u32(const void* p) {
    uint32_t a;
    asm("{ .reg .u64 t; cvta.to.shared.u64 t, %1; cvt.u32.u64 %0, t; }" : "=r"(a) : "l"(p));
    return a;
}
// 128B rows; xor-swizzle 16B chunks by row&7 -> conflict-free ldmatrix
__device__ __forceinline__ uint32_t swa(int row, int col16) {
    return (uint32_t)(row * 128 + ((col16 ^ (row & 7)) << 4));
}
__device__ __forceinline__ uint32_t packhi(float a, float b) {
    __nv_bfloat162 t = __floats2bfloat162_rn(a, b);
    return *reinterpret_cast<uint32_t*>(&t);
}
__device__ __forceinline__ uint32_t packlo(float a, float b) {
    float ah = __bfloat162float(__float2bfloat16_rn(a));
    float bh = __bfloat162float(__float2bfloat16_rn(b));
    __nv_bfloat162 t = __floats2bfloat162_rn(a - ah, b - bh);
    return *reinterpret_cast<uint32_t*>(&t);
}
__device__ __forceinline__ float ex2f(float x) {
    float r;
    asm("ex2.approx.ftz.f32 %0, %1;" : "=f"(r) : "f"(x));
    return r;
}

#define CP_ASYNC16(SM, GM) \
    asm volatile("cp.async.cg.shared.global [%0], [%1], 16;" :: "r"(SM), "l"(GM) : "memory")
#define CP_COMMIT()  asm volatile("cp.async.commit_group;" ::: "memory")
#define CP_WAIT0()   asm volatile("cp.async.wait_group 0;" ::: "memory")
#define CP_WAIT1()   asm volatile("cp.async.wait_group 1;" ::: "memory")

#define LDSM_X4(R0,R1,R2,R3,ADDR) \
    asm volatile("ldmatrix.sync.aligned.m8n8.x4.shared.b16 {%0,%1,%2,%3}, [%4];" \
                 : "=r"(R0),"=r"(R1),"=r"(R2),"=r"(R3) : "r"(ADDR))
#define LDSM_X4T(R0,R1,R2,R3,ADDR) \
    asm volatile("ldmatrix.sync.aligned.m8n8.x4.trans.shared.b16 {%0,%1,%2,%3}, [%4];" \
                 : "=r"(R0),"=r"(R1),"=r"(R2),"=r"(R3) : "r"(ADDR))
// D += A * B   (m16n8k16, bf16 in, f32 accum)
#define MMA(D,A,B0,B1) \
    asm volatile("mma.sync.aligned.m16n8k16.row.col.f32.bf16.bf16.f32 " \
                 "{%0,%1,%2,%3},{%4,%5,%6,%7},{%8,%9},{%0,%1,%2,%3};" \
                 : "+f"((D)[0]),"+f"((D)[1]),"+f"((D)[2]),"+f"((D)[3]) \
                 : "r"((A)[0]),"r"((A)[1]),"r"((A)[2]),"r"((A)[3]),"r"(B0),"r"(B1))

// ---------------------------------------------------------------------------
// Pre-pass: K,V fp32 -> bf16 hi/lo scratch.  K scaled by log2(e) so the hot
// loop can use ex2.approx directly on the scores.
// ---------------------------------------------------------------------------
__global__ __launch_bounds__(256)
void kv_convert_kernel(const float* __restrict__ k, const float* __restrict__ v)
{
    const float LOG2E = 1.4426950408889634f;
    int i = blockIdx.x * 256 + threadIdx.x;          // float4 index
    float4 kx = reinterpret_cast<const float4*>(k)[i];
    kx.x *= LOG2E; kx.y *= LOG2E; kx.z *= LOG2E; kx.w *= LOG2E;
    float4 vx = reinterpret_cast<const float4*>(v)[i];
    reinterpret_cast<uint2*>(g_khi)[i] = make_uint2(packhi(kx.x, kx.y), packhi(kx.z, kx.w));
    reinterpret_cast<uint2*>(g_klo)[i] = make_uint2(packlo(kx.x, kx.y), packlo(kx.z, kx.w));
    reinterpret_cast<uint2*>(g_vhi)[i] = make_uint2(packhi(vx.x, vx.y), packhi(vx.z, vx.w));
    reinterpret_cast<uint2*>(g_vlo)[i] = make_uint2(packlo(vx.x, vx.y), packlo(vx.z, vx.w));
}

// ---------------------------------------------------------------------------
// Attention kernel
// ---------------------------------------------------------------------------
__global__ __launch_bounds__(NTHREADS, 3)
void attn_mma_kernel(const float* __restrict__ q,
                     float* __restrict__ out)
{
    __shared__ __align__(1024) char smem[SMEM_BYTES];
    const uint32_t sb = smem_u32(smem);
    const int tid  = threadIdx.x;
    const int w    = tid >> 5;                // warp 0..3
    const int lane = tid & 31;
    const int b     = blockIdx.y;
    const int qbase = blockIdx.x * QT;
    const int wr0   = w * 16;                 // this warp's q-row base in tile

    const size_t kvbase = (size_t)b * SEQ * DIM;   // element offset of this batch

    const __nv_bfloat16* g_arr[4] = { g_khi, g_klo, g_vhi, g_vlo };

    // ---- kick off DMA of tile 0 into buf0 ----
    {
#pragma unroll
        for (int i = 0; i < 16; i++) {
            int arr = i >> 2, rc = (i & 3) * NTHREADS + tid;
            int row = rc >> 3, c16 = rc & 7;
            const char* src = (const char*)(g_arr[arr] + kvbase + row * DIM) + c16 * 16;
            CP_ASYNC16(sb + arr * 8192 + swa(row, c16), src);
        }
        CP_COMMIT();
    }

    // ---- Prologue: stage Q (64x64 f32 -> bf16 hi/lo) into buf1 region ----
    {
        const float* qp = q + ((size_t)b * SEQ + qbase) * DIM;
#pragma unroll
        for (int i = 0; i < (QT * DIM / 4) / NTHREADS; i++) {   // 8 iters
            int idx = i * NTHREADS + tid;
            int row = idx >> 4, f4 = idx & 15;
            float4 x = reinterpret_cast<const float4*>(qp + row * DIM)[f4];
            uint32_t off = swa(row, f4 >> 1) + (f4 & 1) * 8;
            *reinterpret_cast<uint2*>(smem + BUF_STRIDE + off) =
                make_uint2(packhi(x.x, x.y), packhi(x.z, x.w));
            *reinterpret_cast<uint2*>(smem + BUF_STRIDE + 8192 + off) =
                make_uint2(packlo(x.x, x.y), packlo(x.z, x.w));
        }
    }
    __syncthreads();

    // Q fragments (A of m16n8k16): 4 k-chunks of 16, hi and lo
    uint32_t qh[4][4], ql[4][4];
    {
        int arow = wr0 + (lane & 7) + ((lane >> 3) & 1) * 8;
#pragma unroll
        for (int kc = 0; kc < 4; kc++) {
            uint32_t off = swa(arow, kc * 2 + (lane >> 4));
            LDSM_X4(qh[kc][0], qh[kc][1], qh[kc][2], qh[kc][3], sb + BUF_STRIDE + off);
            LDSM_X4(ql[kc][0], ql[kc][1], ql[kc][2], ql[kc][3], sb + BUF_STRIDE + 8192 + off);
        }
    }
    __syncthreads();   // buf1 free for tile-1 prefetch after this

    float oacc[8][4];
#pragma unroll
    for (int nt = 0; nt < 8; nt++)
#pragma unroll
        for (int i = 0; i < 4; i++) oacc[nt][i] = 0.0f;
    // row-sum accumulator, fed by MMA against all-ones B.
    // After the ones-MMA every column holds the FULL row sum:
    // lsacc[0] = sum for row r, lsacc[2] = sum for row r+8.
    float lsacc[4] = {0.0f, 0.0f, 0.0f, 0.0f};
    const uint32_t ONES = 0x3F803F80u;   // bf16x2 {1.0, 1.0}

    // lane mapping for x4 B-operand ldmatrix
    const int m8 = lane >> 3;     // which 8x8 matrix this lane addresses
    const int r8 = lane & 7;

    for (int t = 0; t < NTILES; t++) {
        const uint32_t bufb = sb + (uint32_t)(t & 1) * BUF_STRIDE;

        // ---- prefetch tile t+1 into the other buffer; wait for tile t ----
        if (t + 1 < NTILES) {
            const size_t toff = kvbase + (size_t)(t + 1) * KT * DIM;
            const uint32_t nb = sb + (uint32_t)((t + 1) & 1) * BUF_STRIDE;
#pragma unroll
            for (int i = 0; i < 16; i++) {
                int arr = i >> 2, rc = (i & 3) * NTHREADS + tid;
                int row = rc >> 3, c16 = rc & 7;
                const char* src = (const char*)(g_arr[arr] + toff + row * DIM) + c16 * 16;
                CP_ASYNC16(nb + arr * 8192 + swa(row, c16), src);
            }
            CP_COMMIT();
            CP_WAIT1();          // oldest group (tile t) complete
        } else {
            CP_WAIT0();
        }
        __syncthreads();

        // ---- MMA1: S[16,64] = Qhi.Khi^T + Qhi.Klo^T + Qlo.Khi^T ----
        // (scores are already in log2 units: K pre-scaled by log2e)
        float sacc[8][4];
#pragma unroll
        for (int nt = 0; nt < 8; nt++)
#pragma unroll
            for (int i = 0; i < 4; i++) sacc[nt][i] = 0.0f;

#pragma unroll
        for (int half = 0; half < 2; half++) {
#pragma unroll
            for (int kc = 0; kc < 4; kc++) {
#pragma unroll
                for (int ntl = 0; ntl < 2; ntl++) {
                    int ntp = half * 2 + ntl;
                    int krow  = (ntp * 2 + (m8 >> 1)) * 8 + r8;
                    uint32_t off = swa(krow, kc * 2 + (m8 & 1));
                    uint32_t bh0, bh1, bh2, bh3, bl0, bl1, bl2, bl3;
                    LDSM_X4(bh0, bh1, bh2, bh3, bufb + T_KHI + off);
                    LDSM_X4(bl0, bl1, bl2, bl3, bufb + T_KLO + off);
                    MMA(sacc[2*ntp],   qh[kc], bh0, bh1);
                    MMA(sacc[2*ntp+1], qh[kc], bh2, bh3);
                    MMA(sacc[2*ntp],   qh[kc], bl0, bl1);
                    MMA(sacc[2*ntp+1], qh[kc], bl2, bl3);
                    MMA(sacc[2*ntp],   ql[kc], bh0, bh1);
                    MMA(sacc[2*ntp+1], ql[kc], bh2, bh3);
                }
            }
        }

        // ---- per key-half: exp(S) -> rn-rounded Phi fragments, then MMA2.
        //      Row-sum computed by MMA against all-ones B (lsacc) -> exact
        //      cancellation w.r.t. the numerator, zero ALU bookkeeping.
#pragma unroll
        for (int half = 0; half < 2; half++) {
            uint32_t ph[2][4];
#pragma unroll
            for (int ntl = 0; ntl < 4; ntl++) {
                int nt = half * 4 + ntl;
                float p0 = ex2f(sacc[nt][0]);
                float p1 = ex2f(sacc[nt][1]);
                float p2 = ex2f(sacc[nt][2]);
                float p3 = ex2f(sacc[nt][3]);
                int kcl = ntl >> 1, h = (ntl & 1) * 2;
                ph[kcl][h]     = packhi(p0, p1);
                ph[kcl][h + 1] = packhi(p2, p3);
            }

            // MMA2 for key-chunks of this half: O += Phi.Vhi + Phi.Vlo
            // plus one ones-MMA per key-chunk for the row sum.
#pragma unroll
            for (int kcl = 0; kcl < 2; kcl++) {
                int kcg = half * 2 + kcl;
                MMA(lsacc, ph[kcl], ONES, ONES);
#pragma unroll
                for (int ntp = 0; ntp < 4; ntp++) {
                    int vrow = kcg * 16 + (m8 & 1) * 8 + r8;
                    uint32_t off = swa(vrow, ntp * 2 + (m8 >> 1));
                    uint32_t bh0, bh1, bh2, bh3, bl0, bl1, bl2, bl3;
                    LDSM_X4T(bh0, bh1, bh2, bh3, bufb + T_VHI + off);
                    LDSM_X4T(bl0, bl1, bl2, bl3, bufb + T_VLO + off);
                    MMA(oacc[2*ntp],   ph[kcl], bh0, bh1);
                    MMA(oacc[2*ntp+1], ph[kcl], bh2, bh3);
                    MMA(oacc[2*ntp],   ph[kcl], bl0, bl1);
                    MMA(oacc[2*ntp+1], ph[kcl], bl2, bl3);
                }
            }
        }
        __syncthreads();   // tile t reads done -> buffer reusable next iter
    }

    // ---- row sums: already complete per-lane (ones-MMA fills every column
    //      with the full sum) -> NO cross-lane reduction.
    const float inv0 = 1.0f / lsacc[0];
    const float inv1 = 1.0f / lsacc[2];

    // ---- normalize + store ----
    {
        const int r = lane >> 2, c = lane & 3;
        float* op0 = out + ((size_t)b * SEQ + qbase + wr0 + r) * DIM;
        float* op1 = op0 + 8 * DIM;
#pragma unroll
        for (int nt = 0; nt < 8; nt++) {
            float2 t0 = make_float2(oacc[nt][0] * inv0, oacc[nt][1] * inv0);
            float2 t1 = make_float2(oacc[nt][2] * inv1, oacc[nt][3] * inv1);
            *reinterpret_cast<float2*>(op0 + nt * 8 + 2 * c) = t0;
            *reinterpret_cast<float2*>(op1 + nt * 8 + 2 * c) = t1;
        }
    }
}

extern "C" void kernel_launch(void* const* d_in, const int* in_sizes, int n_in,
                              void* d_out, int out_size)
{
    const float* q = (const float*)d_in[0];
    const float* k = (const float*)d_in[1];
    const float* v = (const float*)d_in[2];
    float* out = (float*)d_out;

    kv_convert_kernel<<<KV_ELEMS / 4 / 256, 256>>>(k, v);

    dim3 grid(SEQ / QT, BATCH);
    attn_mma_kernel<<<grid, NTHREADS>>>(q, out);
}